// round 2
// baseline (speedup 1.0000x reference)
#include <cuda_runtime.h>
#include <math.h>

#define D   128
#define B   128
#define S   200
#define NQ  10000
#define NC  500

// ---------------- scratch tables (device globals; no allocation) ----------------
__device__ float g_M1[D*D];      // W_fuse_top @ W_absorb_top
__device__ float g_M2[D*D];      // W_fuse_top @ W_forget_bot
__device__ float g_UT[100*D];    // embed_use_time @ W_absorb_mid
__device__ float g_HA[12*D];     // embed_hint_attempt @ W_absorb_bot
__device__ float g_IT[100*D];    // embed_interval_time @ W_forget_mid
__device__ float g_s1[D];        // colsum(W_fuse_bot)
__device__ float g_v1[D];        // s1 @ W_absorb_top
__device__ float g_v2[D];        // s1 @ W_forget_bot
__device__ float g_bA[D];        // b_fuse @ W_absorb_top + b_absorb
__device__ float g_bF[D];        // b_fuse @ W_forget_bot + b_forget
__device__ float g_P1[NQ*D];     // embed_question @ M1
__device__ float g_P2[NQ*D];     // embed_question @ M2
__device__ float g_qd[NQ];       // 10*sigmoid(disc)
__device__ float g_qdm[NQ];      // sum_k qdiff_k * mask_k  (per question)
__device__ float g_rnC[NC];      // 1/max(|concept|,eps)

// ---------------- prepA: small composite mats + tables ----------------
// blocks: [0,128) M1 rows | [128,256) M2 rows | [256,356) UT | [356,368) HA |
//         [368,468) IT | 468 s1 | 469 bA | 470 bF | [471,475) rnC | [475,554) qd
__global__ void __launch_bounds__(128) prepA_kernel(
    const float* __restrict__ Wfuse, const float* __restrict__ bfuse,
    const float* __restrict__ Wabs,  const float* __restrict__ babs,
    const float* __restrict__ Wfor,  const float* __restrict__ bfor,
    const float* __restrict__ EQd,   const float* __restrict__ EC,
    const float* __restrict__ EIT,   const float* __restrict__ EUT,
    const float* __restrict__ EHA)
{
    __shared__ float sh[D];
    const int tid = threadIdx.x;
    const int bid = blockIdx.x;

    if (bid < 468) {
        const float* vrow; const float* Wb; float* outp;
        if (bid < 128)      { vrow = Wfuse + bid*D;        Wb = Wabs;           outp = g_M1 + bid*D; }
        else if (bid < 256) { vrow = Wfuse + (bid-128)*D;  Wb = Wfor + 2*D*D;   outp = g_M2 + (bid-128)*D; }
        else if (bid < 356) { vrow = EUT + (bid-256)*D;    Wb = Wabs + D*D;     outp = g_UT + (bid-256)*D; }
        else if (bid < 368) { vrow = EHA + (bid-356)*D;    Wb = Wabs + 2*D*D;   outp = g_HA + (bid-356)*D; }
        else                { vrow = EIT + (bid-368)*D;    Wb = Wfor + D*D;     outp = g_IT + (bid-368)*D; }
        sh[tid] = vrow[tid];
        __syncthreads();
        float a0=0.f,a1=0.f,a2=0.f,a3=0.f;
        #pragma unroll 8
        for (int jj=0; jj<D; jj+=4){
            a0 += sh[jj+0]*Wb[(jj+0)*D+tid];
            a1 += sh[jj+1]*Wb[(jj+1)*D+tid];
            a2 += sh[jj+2]*Wb[(jj+2)*D+tid];
            a3 += sh[jj+3]*Wb[(jj+3)*D+tid];
        }
        outp[tid] = (a0+a1)+(a2+a3);
    } else if (bid == 468) {
        float s=0.f;
        #pragma unroll 8
        for (int k=0;k<D;k++) s += Wfuse[(D+k)*D+tid];
        g_s1[tid]=s;
    } else if (bid == 469) {
        sh[tid]=bfuse[tid]; __syncthreads();
        float a=0.f;
        #pragma unroll 8
        for (int k=0;k<D;k++) a += sh[k]*Wabs[k*D+tid];
        g_bA[tid] = a + babs[tid];
    } else if (bid == 470) {
        sh[tid]=bfuse[tid]; __syncthreads();
        float a=0.f;
        #pragma unroll 8
        for (int k=0;k<D;k++) a += sh[k]*Wfor[(2*D+k)*D+tid];
        g_bF[tid] = a + bfor[tid];
    } else if (bid < 475) {
        int c = (bid-471)*128 + tid;
        if (c < NC){
            float s=0.f;
            #pragma unroll 8
            for (int dd=0; dd<D; dd++){ float e = EC[c*D+dd]; s += e*e; }
            g_rnC[c] = 1.f/fmaxf(sqrtf(s), 1e-8f);
        }
    } else {
        int q = (bid-475)*128 + tid;
        if (q < NQ) g_qd[q] = 10.f/(1.f+__expf(-EQd[q]));
    }
}

// ---------------- prepB: P1/P2 question tables + qdm, plus v1/v2 ----------------
#define NBQ 148
#define QPB 68
#define SMEM_B ((2*D*D + 4*D) * (int)sizeof(float))

__global__ void __launch_bounds__(256) prepB_kernel(
    const float* __restrict__ EQ, const float* __restrict__ EC,
    const int* __restrict__ q2c, const int* __restrict__ q2cm,
    const float* __restrict__ Wabs, const float* __restrict__ Wfor)
{
    const int tid = threadIdx.x;
    const int bid = blockIdx.x;

    if (bid >= NBQ){                       // v1 / v2 blocks (need g_s1 from prepA)
        __shared__ float s1s[D];
        if (tid < D) s1s[tid] = g_s1[tid];
        __syncthreads();
        if (tid < D){
            const float* Wb = (bid==NBQ) ? Wabs : (Wfor + 2*D*D);
            float a=0.f;
            #pragma unroll 8
            for (int jj=0;jj<D;jj++) a += s1s[jj]*Wb[jj*D+tid];
            if (bid==NBQ) g_v1[tid]=a; else g_v2[tid]=a;
        }
        return;
    }

    extern __shared__ float smem[];
    float* M1s = smem;            // D*D
    float* M2s = smem + D*D;      // D*D
    float* E4  = smem + 2*D*D;    // 4 questions interleaved: E4[jj*4+q]

    for (int i=tid; i<D*D; i+=256){ M1s[i]=g_M1[i]; M2s[i]=g_M2[i]; }
    __syncthreads();

    const int qbase = bid*QPB;
    for (int gg=0; gg<QPB; gg+=4){
        const int qb = qbase+gg;
        for (int i=tid; i<4*D; i+=256){
            int q = i>>7, jj = i&127;
            int qq = qb+q;
            E4[jj*4+q] = (qq<NQ) ? EQ[qq*D+jj] : 0.f;
        }
        __syncthreads();
        {
            const int halfp = tid>>7, jj = tid&127;
            const float* Ms = halfp ? M2s : M1s;
            float a0=0.f,a1=0.f,a2=0.f,a3=0.f;
            const float4* Ev = (const float4*)E4;
            #pragma unroll 8
            for (int jk=0; jk<D; jk++){
                float4 e = Ev[jk];
                float m = Ms[jk*D+jj];
                a0 += e.x*m; a1 += e.y*m; a2 += e.z*m; a3 += e.w*m;
            }
            float* P = halfp ? g_P2 : g_P1;
            if (qb+0<NQ) P[(qb+0)*D+jj]=a0;
            if (qb+1<NQ) P[(qb+1)*D+jj]=a1;
            if (qb+2<NQ) P[(qb+2)*D+jj]=a2;
            if (qb+3<NQ) P[(qb+3)*D+jj]=a3;
        }
        {   // qdm for the 4 questions, warps 0..3
            const int w = tid>>5, lane = tid&31;
            if (w<4 && (qb+w)<NQ){
                const int q = qb+w;
                int4 cid = ((const int4*)q2c)[q];
                float nrm=0.f,d0=0.f,d1=0.f,d2=0.f,d3=0.f;
                #pragma unroll
                for (int r=0;r<4;r++){
                    int jj = lane + 32*r;
                    float e = E4[jj*4+w];
                    nrm += e*e;
                    d0 += e*EC[cid.x*D+jj];
                    d1 += e*EC[cid.y*D+jj];
                    d2 += e*EC[cid.z*D+jj];
                    d3 += e*EC[cid.w*D+jj];
                }
                #pragma unroll
                for (int off=16; off; off>>=1){
                    nrm += __shfl_down_sync(0xffffffffu, nrm, off);
                    d0  += __shfl_down_sync(0xffffffffu, d0, off);
                    d1  += __shfl_down_sync(0xffffffffu, d1, off);
                    d2  += __shfl_down_sync(0xffffffffu, d2, off);
                    d3  += __shfl_down_sync(0xffffffffu, d3, off);
                }
                if (lane==0){
                    float rq = 1.f/fmaxf(sqrtf(nrm), 1e-8f);
                    int4 mm = ((const int4*)q2cm)[q];
                    float qdm =
                        0.5f*(d0*rq*g_rnC[cid.x]+1.f)*(float)mm.x +
                        0.5f*(d1*rq*g_rnC[cid.y]+1.f)*(float)mm.y +
                        0.5f*(d2*rq*g_rnC[cid.z]+1.f)*(float)mm.z +
                        0.5f*(d3*rq*g_rnC[cid.w]+1.f)*(float)mm.w;
                    g_qdm[q]=qdm;
                }
            }
        }
        __syncthreads();
    }
}

// ---------------- scan: one CTA per batch row, sequential recurrence ----------------
__global__ void __launch_bounds__(256,1) scan_kernel(
    const int* __restrict__ qseq, const int* __restrict__ haseq,
    const int* __restrict__ cseq, const int* __restrict__ itseq,
    const int* __restrict__ utseq,
    const int* __restrict__ q2c, const int* __restrict__ q2cm,
    const float* __restrict__ EC, const float* __restrict__ Wfor,
    const float* __restrict__ lat0, float* __restrict__ out)
{
    __shared__ __align__(16) float lps[2][D];
    __shared__ float part[256];
    __shared__ float red[8];
    __shared__ float v1s[D], v2s[D], bAs[D], bFs[D];
    __shared__ int sq[S], sha[S], sc[S], sit[S], sut[S];

    const int b   = blockIdx.x;
    const int tid = threadIdx.x;
    const int half = tid >> 7;
    const int j    = tid & 127;
    const int w_id = tid >> 5;
    const int lane = tid & 31;

    // W_forget top [D,D]: thread (half,j) holds rows half*64..half*64+63 of column j
    float w[64];
    #pragma unroll
    for (int kk=0; kk<64; kk++) w[kk] = Wfor[(half*64+kk)*D + j];

    for (int i=tid; i<S; i+=256){
        sq[i]=qseq[b*S+i]; sha[i]=haseq[b*S+i]; sc[i]=cseq[b*S+i];
        sit[i]=itseq[b*S+i]; sut[i]=utseq[b*S+i];
    }
    if (half==0){
        v1s[j]=g_v1[j]; v2s[j]=g_v2[j]; bAs[j]=g_bA[j]; bFs[j]=g_bF[j];
        lps[0][j]=lat0[b*D+j];
    }
    __syncthreads();

    int pb = 0;
    for (int t=0; t<S-1; t++){
        const float* lpp = lps[pb];

        // ---- prefetch all per-step table data before the matvec ----
        float a_p1=0.f,a_p2=0.f,a_ut=0.f,a_ha=0.f,a_it=0.f,ct=0.f;
        if (half==0){
            int qt = sq[t]; ct = (float)sc[t];
            a_p1 = g_P1[qt*D+j];
            a_p2 = g_P2[qt*D+j];
            a_ut = g_UT[sut[t]*D+j];
            a_ha = g_HA[sha[t]*D+j];
            a_it = g_IT[sit[t]*D+j];
        }
        float e0=0.f,e1=0.f,e2=0.f,e3=0.f,rn=0.f;
        if (w_id < 4){
            int cid = q2c[sq[t+1]*4 + w_id];
            const float* ecp = &EC[cid*D + lane];
            e0=ecp[0]; e1=ecp[32]; e2=ecp[64]; e3=ecp[96];
            rn = g_rnC[cid];
        }
        float qd1=0.f, qdmt=0.f; int4 mm;
        if (tid==0){
            qd1 = g_qd[sq[t+1]]; qdmt = g_qdm[sq[t]];
            mm = ((const int4*)q2cm)[sq[t]];
        }

        // ---- matvec: lp @ Wg_top, split over two halves of k ----
        float p0=0.f,p1=0.f,p2=0.f,p3=0.f;
        #pragma unroll
        for (int kk=0; kk<64; kk+=4){
            float4 lv = *(const float4*)&lpp[half*64+kk];
            p0 += lv.x*w[kk];   p1 += lv.y*w[kk+1];
            p2 += lv.z*w[kk+2]; p3 += lv.w*w[kk+3];
        }
        part[tid] = (p0+p1)+(p2+p3);
        __syncthreads();

        // ---- gate + update ----
        if (half==0){
            float avec = a_p1 + ct*v1s[j] + a_ut + a_ha + bAs[j];
            float cpre = a_p2 + ct*v2s[j] + a_it + bFs[j];
            float z = part[j] + part[D+j] + cpre;
            float f = 1.f/(1.f+__expf(-z));
            lps[pb^1][j] = lpp[j]*f + avec;
        }
        __syncthreads();
        pb ^= 1;
        const float* lc = lps[pb];

        // ---- dot products with next-step concepts + norm ----
        if (w_id < 5){
            float acc;
            if (w_id < 4){
                acc = lc[lane]*e0 + lc[lane+32]*e1 + lc[lane+64]*e2 + lc[lane+96]*e3;
            } else {
                float x0=lc[lane], x1=lc[lane+32], x2=lc[lane+64], x3=lc[lane+96];
                acc = x0*x0 + x1*x1 + x2*x2 + x3*x3;
            }
            #pragma unroll
            for (int o=16;o;o>>=1) acc += __shfl_down_sync(0xffffffffu, acc, o);
            if (lane==0) red[w_id] = (w_id<4) ? acc*rn : acc;
        }
        __syncthreads();

        if (tid==0){
            float rl = 1.f/fmaxf(sqrtf(red[4]), 1e-8f);
            float s = 0.5f*((red[0]*rl+1.f)*(float)mm.x + (red[1]*rl+1.f)*(float)mm.y
                          + (red[2]*rl+1.f)*(float)mm.z + (red[3]*rl+1.f)*(float)mm.w);
            float logit = qd1 * (s - qdmt);
            out[b*S+t] = 1.f/(1.f+__expf(-logit));
        }
        __syncthreads();
    }
    if (tid==0) out[b*S + (S-1)] = 0.f;
}

extern "C" void kernel_launch(void* const* d_in, const int* in_sizes, int n_in,
                              void* d_out, int out_size)
{
    const int*   qseq  = (const int*)  d_in[0];
    const int*   haseq = (const int*)  d_in[1];
    const int*   cseq  = (const int*)  d_in[2];
    const int*   itseq = (const int*)  d_in[3];
    const int*   utseq = (const int*)  d_in[4];
    const int*   q2c   = (const int*)  d_in[5];
    const int*   q2cm  = (const int*)  d_in[6];
    const float* EQ    = (const float*)d_in[7];
    const float* EQd   = (const float*)d_in[8];
    const float* EC    = (const float*)d_in[9];
    const float* EIT   = (const float*)d_in[10];
    const float* EUT   = (const float*)d_in[11];
    const float* EHA   = (const float*)d_in[12];
    const float* Wfuse = (const float*)d_in[13];
    const float* bfuse = (const float*)d_in[14];
    const float* Wabs  = (const float*)d_in[15];
    const float* babs  = (const float*)d_in[16];
    const float* Wfor  = (const float*)d_in[17];
    const float* bfor  = (const float*)d_in[18];
    const float* lat0  = (const float*)d_in[19];
    float* out = (float*)d_out;

    cudaFuncSetAttribute(prepB_kernel,
                         cudaFuncAttributeMaxDynamicSharedMemorySize, SMEM_B);

    prepA_kernel<<<554, 128>>>(Wfuse, bfuse, Wabs, babs, Wfor, bfor,
                               EQd, EC, EIT, EUT, EHA);
    prepB_kernel<<<NBQ+2, 256, SMEM_B>>>(EQ, EC, q2c, q2cm, Wabs, Wfor);
    scan_kernel<<<B, 256>>>(qseq, haseq, cseq, itseq, utseq,
                            q2c, q2cm, EC, Wfor, lat0, out);
}

// round 3
// speedup vs baseline: 1.1585x; 1.1585x over previous
#include <cuda_runtime.h>
#include <math.h>

#define D   128
#define B   128
#define S   200
#define NQ  10000
#define NC  500

// ---------------- scratch tables (device globals; no allocation) ----------------
__device__ float g_M1[D*D];      // W_fuse_top @ W_absorb_top
__device__ float g_M2[D*D];      // W_fuse_top @ W_forget_bot
__device__ float g_UT[100*D];    // embed_use_time @ W_absorb_mid
__device__ float g_HA[12*D];     // embed_hint_attempt @ W_absorb_bot
__device__ float g_IT[100*D];    // embed_interval_time @ W_forget_mid
__device__ float g_s1[D];        // colsum(W_fuse_bot)
__device__ float g_v1[D];        // s1 @ W_absorb_top
__device__ float g_v2[D];        // s1 @ W_forget_bot
__device__ float g_bA[D];        // b_fuse @ W_absorb_top + b_absorb
__device__ float g_bF[D];        // b_fuse @ W_forget_bot + b_forget
__device__ float g_P1[NQ*D];     // embed_question @ M1
__device__ float g_P2[NQ*D];     // embed_question @ M2
__device__ float g_qd[NQ];       // 10*sigmoid(disc)
__device__ float g_qdm[NQ];      // sum_k qdiff_k * mask_k  (per question)
__device__ float g_rnC[NC];      // 1/max(|concept|,eps)

// packed f32x2 fma (sm_100+). d = a*b + d, elementwise on the two fp32 halves.
__device__ __forceinline__ void ffma2(unsigned long long &d,
                                      unsigned long long a, unsigned long long b){
    asm("fma.rn.f32x2 %0, %1, %2, %0;" : "+l"(d) : "l"(a), "l"(b));
}
__device__ __forceinline__ float ulo(unsigned long long v){ return __uint_as_float((unsigned)v); }
__device__ __forceinline__ float uhi(unsigned long long v){ return __uint_as_float((unsigned)(v>>32)); }

// ---------------- prepA: small composite mats + tables ----------------
__global__ void __launch_bounds__(128) prepA_kernel(
    const float* __restrict__ Wfuse, const float* __restrict__ bfuse,
    const float* __restrict__ Wabs,  const float* __restrict__ babs,
    const float* __restrict__ Wfor,  const float* __restrict__ bfor,
    const float* __restrict__ EQd,   const float* __restrict__ EC,
    const float* __restrict__ EIT,   const float* __restrict__ EUT,
    const float* __restrict__ EHA)
{
    __shared__ float sh[D];
    const int tid = threadIdx.x;
    const int bid = blockIdx.x;

    if (bid < 468) {
        const float* vrow; const float* Wb; float* outp;
        if (bid < 128)      { vrow = Wfuse + bid*D;        Wb = Wabs;           outp = g_M1 + bid*D; }
        else if (bid < 256) { vrow = Wfuse + (bid-128)*D;  Wb = Wfor + 2*D*D;   outp = g_M2 + (bid-128)*D; }
        else if (bid < 356) { vrow = EUT + (bid-256)*D;    Wb = Wabs + D*D;     outp = g_UT + (bid-256)*D; }
        else if (bid < 368) { vrow = EHA + (bid-356)*D;    Wb = Wabs + 2*D*D;   outp = g_HA + (bid-356)*D; }
        else                { vrow = EIT + (bid-368)*D;    Wb = Wfor + D*D;     outp = g_IT + (bid-368)*D; }
        sh[tid] = vrow[tid];
        __syncthreads();
        float a0=0.f,a1=0.f,a2=0.f,a3=0.f,a4=0.f,a5=0.f,a6=0.f,a7=0.f;
        #pragma unroll
        for (int jj=0; jj<D; jj+=8){
            a0 += sh[jj+0]*Wb[(jj+0)*D+tid];
            a1 += sh[jj+1]*Wb[(jj+1)*D+tid];
            a2 += sh[jj+2]*Wb[(jj+2)*D+tid];
            a3 += sh[jj+3]*Wb[(jj+3)*D+tid];
            a4 += sh[jj+4]*Wb[(jj+4)*D+tid];
            a5 += sh[jj+5]*Wb[(jj+5)*D+tid];
            a6 += sh[jj+6]*Wb[(jj+6)*D+tid];
            a7 += sh[jj+7]*Wb[(jj+7)*D+tid];
        }
        outp[tid] = ((a0+a1)+(a2+a3))+((a4+a5)+(a6+a7));
    } else if (bid == 468) {
        float a0=0.f,a1=0.f,a2=0.f,a3=0.f;
        #pragma unroll
        for (int k=0;k<D;k+=4){
            a0 += Wfuse[(D+k+0)*D+tid]; a1 += Wfuse[(D+k+1)*D+tid];
            a2 += Wfuse[(D+k+2)*D+tid]; a3 += Wfuse[(D+k+3)*D+tid];
        }
        g_s1[tid]=(a0+a1)+(a2+a3);
    } else if (bid == 469) {
        sh[tid]=bfuse[tid]; __syncthreads();
        float a0=0.f,a1=0.f,a2=0.f,a3=0.f;
        #pragma unroll
        for (int k=0;k<D;k+=4){
            a0 += sh[k+0]*Wabs[(k+0)*D+tid]; a1 += sh[k+1]*Wabs[(k+1)*D+tid];
            a2 += sh[k+2]*Wabs[(k+2)*D+tid]; a3 += sh[k+3]*Wabs[(k+3)*D+tid];
        }
        g_bA[tid] = (a0+a1)+(a2+a3) + babs[tid];
    } else if (bid == 470) {
        sh[tid]=bfuse[tid]; __syncthreads();
        float a0=0.f,a1=0.f,a2=0.f,a3=0.f;
        #pragma unroll
        for (int k=0;k<D;k+=4){
            a0 += sh[k+0]*Wfor[(2*D+k+0)*D+tid]; a1 += sh[k+1]*Wfor[(2*D+k+1)*D+tid];
            a2 += sh[k+2]*Wfor[(2*D+k+2)*D+tid]; a3 += sh[k+3]*Wfor[(2*D+k+3)*D+tid];
        }
        g_bF[tid] = (a0+a1)+(a2+a3) + bfor[tid];
    } else if (bid < 475) {
        int c = (bid-471)*128 + tid;
        if (c < NC){
            float s=0.f;
            #pragma unroll
            for (int dd=0; dd<D; dd+=4){
                float4 e = *(const float4*)&EC[c*D+dd];
                s += e.x*e.x + e.y*e.y + e.z*e.z + e.w*e.w;
            }
            g_rnC[c] = 1.f/fmaxf(sqrtf(s), 1e-8f);
        }
    } else {
        int q = (bid-475)*128 + tid;
        if (q < NQ) g_qd[q] = 10.f/(1.f+__expf(-EQd[q]));
    }
}

// ---------------- prepB: P1/P2 question tables + qdm, plus v1/v2 ----------------
#define NBQ 148
#define QPB 68
#define SMEM_B ((2*D*D + 4*D) * (int)sizeof(float))

__global__ void __launch_bounds__(256) prepB_kernel(
    const float* __restrict__ EQ, const float* __restrict__ EC,
    const int* __restrict__ q2c, const int* __restrict__ q2cm,
    const float* __restrict__ Wabs, const float* __restrict__ Wfor)
{
    const int tid = threadIdx.x;
    const int bid = blockIdx.x;

    if (bid >= NBQ){                       // v1 / v2 blocks (need g_s1 from prepA)
        __shared__ float s1s[D];
        if (tid < D) s1s[tid] = g_s1[tid];
        __syncthreads();
        if (tid < D){
            const float* Wb = (bid==NBQ) ? Wabs : (Wfor + 2*D*D);
            float a0=0.f,a1=0.f,a2=0.f,a3=0.f;
            #pragma unroll
            for (int jj=0;jj<D;jj+=4){
                a0 += s1s[jj+0]*Wb[(jj+0)*D+tid]; a1 += s1s[jj+1]*Wb[(jj+1)*D+tid];
                a2 += s1s[jj+2]*Wb[(jj+2)*D+tid]; a3 += s1s[jj+3]*Wb[(jj+3)*D+tid];
            }
            float a = (a0+a1)+(a2+a3);
            if (bid==NBQ) g_v1[tid]=a; else g_v2[tid]=a;
        }
        return;
    }

    extern __shared__ float smem[];
    float* M1s = smem;            // D*D
    float* M2s = smem + D*D;      // D*D
    float* E4  = smem + 2*D*D;    // 4 questions interleaved: E4[jj*4+q]

    for (int i=tid; i<D*D; i+=256){ M1s[i]=g_M1[i]; M2s[i]=g_M2[i]; }
    __syncthreads();

    const int qbase = bid*QPB;
    for (int gg=0; gg<QPB; gg+=4){
        const int qb = qbase+gg;
        for (int i=tid; i<4*D; i+=256){
            int q = i>>7, jj = i&127;
            int qq = qb+q;
            E4[jj*4+q] = (qq<NQ) ? EQ[qq*D+jj] : 0.f;
        }
        __syncthreads();
        {
            const int halfp = tid>>7, jj = tid&127;
            const float* Ms = halfp ? M2s : M1s;
            float a0=0.f,a1=0.f,a2=0.f,a3=0.f;
            const float4* Ev = (const float4*)E4;
            #pragma unroll 8
            for (int jk=0; jk<D; jk++){
                float4 e = Ev[jk];
                float m = Ms[jk*D+jj];
                a0 += e.x*m; a1 += e.y*m; a2 += e.z*m; a3 += e.w*m;
            }
            float* P = halfp ? g_P2 : g_P1;
            if (qb+0<NQ) P[(qb+0)*D+jj]=a0;
            if (qb+1<NQ) P[(qb+1)*D+jj]=a1;
            if (qb+2<NQ) P[(qb+2)*D+jj]=a2;
            if (qb+3<NQ) P[(qb+3)*D+jj]=a3;
        }
        {   // qdm for the 4 questions, warps 0..3
            const int w = tid>>5, lane = tid&31;
            if (w<4 && (qb+w)<NQ){
                const int q = qb+w;
                int4 cid = ((const int4*)q2c)[q];
                float nrm=0.f,d0=0.f,d1=0.f,d2=0.f,d3=0.f;
                #pragma unroll
                for (int r=0;r<4;r++){
                    int jj = lane + 32*r;
                    float e = E4[jj*4+w];
                    nrm += e*e;
                    d0 += e*EC[cid.x*D+jj];
                    d1 += e*EC[cid.y*D+jj];
                    d2 += e*EC[cid.z*D+jj];
                    d3 += e*EC[cid.w*D+jj];
                }
                #pragma unroll
                for (int off=16; off; off>>=1){
                    nrm += __shfl_down_sync(0xffffffffu, nrm, off);
                    d0  += __shfl_down_sync(0xffffffffu, d0, off);
                    d1  += __shfl_down_sync(0xffffffffu, d1, off);
                    d2  += __shfl_down_sync(0xffffffffu, d2, off);
                    d3  += __shfl_down_sync(0xffffffffu, d3, off);
                }
                if (lane==0){
                    float rq = 1.f/fmaxf(sqrtf(nrm), 1e-8f);
                    int4 mm = ((const int4*)q2cm)[q];
                    float qdm =
                        0.5f*(d0*rq*g_rnC[cid.x]+1.f)*(float)mm.x +
                        0.5f*(d1*rq*g_rnC[cid.y]+1.f)*(float)mm.y +
                        0.5f*(d2*rq*g_rnC[cid.z]+1.f)*(float)mm.z +
                        0.5f*(d3*rq*g_rnC[cid.w]+1.f)*(float)mm.w;
                    g_qdm[q]=qdm;
                }
            }
        }
        __syncthreads();
    }
}

// ---------------- scan: one CTA per batch row; 8 matvec warps + 1 output warp ----------------
#define SCAN_THREADS 288

// load concept rows + scalars for output step tcur (concepts of q[tcur+1], mask/qdm of q[tcur])
#define OW_LOAD(E, RN0,RN1,RN2,RN3, QDV,QDMV, M0,M1,M2,M3, tcur) do{                    \
    int q1_ = sq[(tcur)+1];                                                              \
    int4 cid_ = __ldg((const int4*)q2c + q1_);                                           \
    const float* e0_ = EC + cid_.x*D + lane;                                             \
    const float* e1_ = EC + cid_.y*D + lane;                                             \
    const float* e2_ = EC + cid_.z*D + lane;                                             \
    const float* e3_ = EC + cid_.w*D + lane;                                             \
    E[0]=e0_[0];  E[1]=e0_[32];  E[2]=e0_[64];  E[3]=e0_[96];                            \
    E[4]=e1_[0];  E[5]=e1_[32];  E[6]=e1_[64];  E[7]=e1_[96];                            \
    E[8]=e2_[0];  E[9]=e2_[32];  E[10]=e2_[64]; E[11]=e2_[96];                           \
    E[12]=e3_[0]; E[13]=e3_[32]; E[14]=e3_[64]; E[15]=e3_[96];                           \
    if (lane==0){                                                                        \
        RN0=g_rnC[cid_.x]; RN1=g_rnC[cid_.y]; RN2=g_rnC[cid_.z]; RN3=g_rnC[cid_.w];      \
        QDV=g_qd[q1_];                                                                   \
        int qt_ = sq[tcur]; QDMV=g_qdm[qt_];                                             \
        int4 mm_ = __ldg((const int4*)q2cm + qt_);                                       \
        M0=(float)mm_.x; M1=(float)mm_.y; M2=(float)mm_.z; M3=(float)mm_.w;              \
    }                                                                                    \
}while(0)

#define OW_DOTS(E, lcv, D0,D1,D2,D3,NV) do{                                              \
    float x0_=(lcv)[lane], x1_=(lcv)[lane+32], x2_=(lcv)[lane+64], x3_=(lcv)[lane+96];   \
    D0 = x0_*E[0]  + x1_*E[1]  + x2_*E[2]  + x3_*E[3];                                   \
    D1 = x0_*E[4]  + x1_*E[5]  + x2_*E[6]  + x3_*E[7];                                   \
    D2 = x0_*E[8]  + x1_*E[9]  + x2_*E[10] + x3_*E[11];                                  \
    D3 = x0_*E[12] + x1_*E[13] + x2_*E[14] + x3_*E[15];                                  \
    NV = x0_*x0_ + x1_*x1_ + x2_*x2_ + x3_*x3_;                                          \
    _Pragma("unroll")                                                                    \
    for (int o_=16;o_;o_>>=1){                                                           \
        D0 += __shfl_down_sync(0xffffffffu, D0, o_);                                     \
        D1 += __shfl_down_sync(0xffffffffu, D1, o_);                                     \
        D2 += __shfl_down_sync(0xffffffffu, D2, o_);                                     \
        D3 += __shfl_down_sync(0xffffffffu, D3, o_);                                     \
        NV += __shfl_down_sync(0xffffffffu, NV, o_);                                     \
    }                                                                                    \
}while(0)

#define OW_TAIL(D0,D1,D2,D3,NV, RN0,RN1,RN2,RN3, QDV,QDMV, M0,M1,M2,M3, tout) do{        \
    float rl_ = 1.f/fmaxf(sqrtf(NV), 1e-8f);                                             \
    float s_ = 0.5f*((D0*RN0*rl_+1.f)*M0 + (D1*RN1*rl_+1.f)*M1                           \
                   + (D2*RN2*rl_+1.f)*M2 + (D3*RN3*rl_+1.f)*M3);                         \
    float lg_ = QDV*(s_-QDMV);                                                           \
    out[b*S+(tout)] = 1.f/(1.f+__expf(-lg_));                                            \
}while(0)

__global__ void __launch_bounds__(SCAN_THREADS,1) scan_kernel(
    const int* __restrict__ qseq, const int* __restrict__ haseq,
    const int* __restrict__ cseq, const int* __restrict__ itseq,
    const int* __restrict__ utseq,
    const int* __restrict__ q2c, const int* __restrict__ q2cm,
    const float* __restrict__ EC, const float* __restrict__ Wfor,
    const float* __restrict__ lat0, float* __restrict__ out)
{
    __shared__ __align__(16) float lps[2][D];
    __shared__ float part[256];
    __shared__ float v1s[D], v2s[D], bAs[D], bFs[D];
    __shared__ int sq[S], sha[S], sc[S], sit[S], sut[S];

    const int b    = blockIdx.x;
    const int tid  = threadIdx.x;
    const int lane = tid & 31;
    const bool ow  = (tid >= 256);          // warp 8 = output warp
    const int half = (tid >> 7) & 1;        // matvec threads only
    const int j    = tid & 127;

    for (int i=tid; i<S; i+=SCAN_THREADS){
        sq[i]=qseq[b*S+i]; sha[i]=haseq[b*S+i]; sc[i]=cseq[b*S+i];
        sit[i]=itseq[b*S+i]; sut[i]=utseq[b*S+i];
    }
    if (tid < D){
        v1s[tid]=g_v1[tid]; v2s[tid]=g_v2[tid]; bAs[tid]=g_bA[tid]; bFs[tid]=g_bF[tid];
        lps[0][tid]=lat0[b*D+tid];
    }

    // W_forget top [D,D], packed over k pairs: thread (half,j) holds k = half*64 .. +63 of column j
    unsigned long long w2[32];
    if (!ow){
        #pragma unroll
        for (int kk=0; kk<32; kk++){
            int k0 = half*64 + 2*kk;
            unsigned lo = __float_as_uint(Wfor[(k0  )*D + j]);
            unsigned hi = __float_as_uint(Wfor[(k0+1)*D + j]);
            w2[kk] = ((unsigned long long)hi << 32) | lo;
        }
    }
    __syncthreads();

    // output-warp ping-pong register state
    float eA[16], eB[16];
    float rnA0=0,rnA1=0,rnA2=0,rnA3=0,qdA=0,qdmA=0,mA0=0,mA1=0,mA2=0,mA3=0;
    float rnB0=0,rnB1=0,rnB2=0,rnB3=0,qdB=0,qdmB=0,mB0=0,mB1=0,mB2=0,mB3=0;
    float d0=0,d1=0,d2=0,d3=0,nv=0;

    int pb = 0;
    float a_p1=0.f,a_p2=0.f,a_ut=0.f,a_ha=0.f,a_it=0.f,ct=0.f;

    for (int t=0; t<S-1; t++){
        // ---------------- phase A ----------------
        if (ow){
            // issue loads for out(t) into set (t&1), then reduce dots for out(t-1) from the other set
            if ((t&1)==0) OW_LOAD(eA, rnA0,rnA1,rnA2,rnA3, qdA,qdmA, mA0,mA1,mA2,mA3, t);
            else          OW_LOAD(eB, rnB0,rnB1,rnB2,rnB3, qdB,qdmB, mB0,mB1,mB2,mB3, t);
            if (t > 0){
                const float* lcv = lps[pb];          // = lc_{t-1}
                if (t&1) OW_DOTS(eA, lcv, d0,d1,d2,d3,nv);
                else     OW_DOTS(eB, lcv, d0,d1,d2,d3,nv);
            }
        } else {
            if (half==0){
                int qt = sq[t]; ct = (float)sc[t];
                a_p1 = g_P1[qt*D+j];
                a_p2 = g_P2[qt*D+j];
                a_ut = g_UT[sut[t]*D+j];
                a_ha = g_HA[sha[t]*D+j];
                a_it = g_IT[sit[t]*D+j];
            }
            // matvec: lp @ W_forget_top with packed f32x2 FMAs
            const ulonglong2* lp4 = (const ulonglong2*)(lps[pb] + half*64);
            unsigned long long acc0=0ull, acc1=0ull, acc2=0ull, acc3=0ull;
            #pragma unroll
            for (int kk=0; kk<16; kk+=2){
                ulonglong2 v0 = lp4[kk];
                ulonglong2 v1 = lp4[kk+1];
                ffma2(acc0, v0.x, w2[2*kk  ]);
                ffma2(acc1, v0.y, w2[2*kk+1]);
                ffma2(acc2, v1.x, w2[2*kk+2]);
                ffma2(acc3, v1.y, w2[2*kk+3]);
            }
            float s = ((ulo(acc0)+uhi(acc0)) + (ulo(acc1)+uhi(acc1)))
                    + ((ulo(acc2)+uhi(acc2)) + (ulo(acc3)+uhi(acc3)));
            part[tid] = s;
        }
        __syncthreads();

        // ---------------- phase B ----------------
        if (!ow){
            if (half==0){
                float avec = a_p1 + ct*v1s[j] + a_ut + a_ha + bAs[j];
                float cpre = a_p2 + ct*v2s[j] + a_it + bFs[j];
                float z = part[j] + part[D+j] + cpre;
                float f = 1.f/(1.f+__expf(-z));
                lps[pb^1][j] = lps[pb][j]*f + avec;
            }
        } else if (t > 0 && lane == 0){
            if (t&1) OW_TAIL(d0,d1,d2,d3,nv, rnA0,rnA1,rnA2,rnA3, qdA,qdmA, mA0,mA1,mA2,mA3, t-1);
            else     OW_TAIL(d0,d1,d2,d3,nv, rnB0,rnB1,rnB2,rnB3, qdB,qdmB, mB0,mB1,mB2,mB3, t-1);
        }
        __syncthreads();
        pb ^= 1;
    }

    // epilogue: emit out(S-2) (its set is (S-2)&1 == 0 -> A), zero last column
    if (ow){
        const float* lcv = lps[pb];                  // = lc_{S-2}
        OW_DOTS(eA, lcv, d0,d1,d2,d3,nv);
        if (lane==0){
            OW_TAIL(d0,d1,d2,d3,nv, rnA0,rnA1,rnA2,rnA3, qdA,qdmA, mA0,mA1,mA2,mA3, S-2);
            out[b*S + (S-1)] = 0.f;
        }
    }
}

extern "C" void kernel_launch(void* const* d_in, const int* in_sizes, int n_in,
                              void* d_out, int out_size)
{
    const int*   qseq  = (const int*)  d_in[0];
    const int*   haseq = (const int*)  d_in[1];
    const int*   cseq  = (const int*)  d_in[2];
    const int*   itseq = (const int*)  d_in[3];
    const int*   utseq = (const int*)  d_in[4];
    const int*   q2c   = (const int*)  d_in[5];
    const int*   q2cm  = (const int*)  d_in[6];
    const float* EQ    = (const float*)d_in[7];
    const float* EQd   = (const float*)d_in[8];
    const float* EC    = (const float*)d_in[9];
    const float* EIT   = (const float*)d_in[10];
    const float* EUT   = (const float*)d_in[11];
    const float* EHA   = (const float*)d_in[12];
    const float* Wfuse = (const float*)d_in[13];
    const float* bfuse = (const float*)d_in[14];
    const float* Wabs  = (const float*)d_in[15];
    const float* babs  = (const float*)d_in[16];
    const float* Wfor  = (const float*)d_in[17];
    const float* bfor  = (const float*)d_in[18];
    const float* lat0  = (const float*)d_in[19];
    float* out = (float*)d_out;

    cudaFuncSetAttribute(prepB_kernel,
                         cudaFuncAttributeMaxDynamicSharedMemorySize, SMEM_B);

    prepA_kernel<<<554, 128>>>(Wfuse, bfuse, Wabs, babs, Wfor, bfor,
                               EQd, EC, EIT, EUT, EHA);
    prepB_kernel<<<NBQ+2, 256, SMEM_B>>>(EQ, EC, q2c, q2cm, Wabs, Wfor);
    scan_kernel<<<B, SCAN_THREADS>>>(qseq, haseq, cseq, itseq, utseq,
                                     q2c, q2cm, EC, Wfor, lat0, out);
}

// round 4
// speedup vs baseline: 1.2834x; 1.1079x over previous
#include <cuda_runtime.h>
#include <math.h>

#define D   128
#define B   128
#define S   200
#define NQ  10000
#define NC  500

// ---------------- scratch tables (device globals; no allocation) ----------------
__device__ float g_M1[D*D];      // W_fuse_top @ W_absorb_top
__device__ float g_M2[D*D];      // W_fuse_top @ W_forget_bot
__device__ float g_UT[100*D];    // embed_use_time @ W_absorb_mid
__device__ float g_HA[12*D];     // embed_hint_attempt @ W_absorb_bot
__device__ float g_IT[100*D];    // embed_interval_time @ W_forget_mid
__device__ float g_s1[D];        // colsum(W_fuse_bot)
__device__ float g_v1[D];        // s1 @ W_absorb_top
__device__ float g_v2[D];        // s1 @ W_forget_bot
__device__ float g_bA[D];        // b_fuse @ W_absorb_top + b_absorb
__device__ float g_bF[D];        // b_fuse @ W_forget_bot + b_forget
__device__ float g_P1[NQ*D];     // embed_question @ M1
__device__ float g_P2[NQ*D];     // embed_question @ M2
__device__ float g_qd[NQ];       // 10*sigmoid(disc)
__device__ float g_qdm[NQ];      // sum_k qdiff_k * mask_k  (per question)
__device__ float g_rnC[NC];      // 1/max(|concept|,eps)

// packed f32x2 fma (sm_100+). d = a*b + d, elementwise on the two fp32 halves.
__device__ __forceinline__ void ffma2(unsigned long long &d,
                                      unsigned long long a, unsigned long long b){
    asm("fma.rn.f32x2 %0, %1, %2, %0;" : "+l"(d) : "l"(a), "l"(b));
}
__device__ __forceinline__ float ulo(unsigned long long v){ return __uint_as_float((unsigned)v); }
__device__ __forceinline__ float uhi(unsigned long long v){ return __uint_as_float((unsigned)(v>>32)); }

// ---------------- prepA: small composite mats + tables ----------------
__global__ void __launch_bounds__(128) prepA_kernel(
    const float* __restrict__ Wfuse, const float* __restrict__ bfuse,
    const float* __restrict__ Wabs,  const float* __restrict__ babs,
    const float* __restrict__ Wfor,  const float* __restrict__ bfor,
    const float* __restrict__ EQd,   const float* __restrict__ EC,
    const float* __restrict__ EIT,   const float* __restrict__ EUT,
    const float* __restrict__ EHA)
{
    __shared__ float sh[D];
    const int tid = threadIdx.x;
    const int bid = blockIdx.x;

    if (bid < 468) {
        const float* vrow; const float* Wb; float* outp;
        if (bid < 128)      { vrow = Wfuse + bid*D;        Wb = Wabs;           outp = g_M1 + bid*D; }
        else if (bid < 256) { vrow = Wfuse + (bid-128)*D;  Wb = Wfor + 2*D*D;   outp = g_M2 + (bid-128)*D; }
        else if (bid < 356) { vrow = EUT + (bid-256)*D;    Wb = Wabs + D*D;     outp = g_UT + (bid-256)*D; }
        else if (bid < 368) { vrow = EHA + (bid-356)*D;    Wb = Wabs + 2*D*D;   outp = g_HA + (bid-356)*D; }
        else                { vrow = EIT + (bid-368)*D;    Wb = Wfor + D*D;     outp = g_IT + (bid-368)*D; }
        sh[tid] = vrow[tid];
        __syncthreads();
        float a0=0.f,a1=0.f,a2=0.f,a3=0.f,a4=0.f,a5=0.f,a6=0.f,a7=0.f;
        #pragma unroll
        for (int jj=0; jj<D; jj+=8){
            a0 += sh[jj+0]*Wb[(jj+0)*D+tid];
            a1 += sh[jj+1]*Wb[(jj+1)*D+tid];
            a2 += sh[jj+2]*Wb[(jj+2)*D+tid];
            a3 += sh[jj+3]*Wb[(jj+3)*D+tid];
            a4 += sh[jj+4]*Wb[(jj+4)*D+tid];
            a5 += sh[jj+5]*Wb[(jj+5)*D+tid];
            a6 += sh[jj+6]*Wb[(jj+6)*D+tid];
            a7 += sh[jj+7]*Wb[(jj+7)*D+tid];
        }
        outp[tid] = ((a0+a1)+(a2+a3))+((a4+a5)+(a6+a7));
    } else if (bid == 468) {
        float a0=0.f,a1=0.f,a2=0.f,a3=0.f;
        #pragma unroll
        for (int k=0;k<D;k+=4){
            a0 += Wfuse[(D+k+0)*D+tid]; a1 += Wfuse[(D+k+1)*D+tid];
            a2 += Wfuse[(D+k+2)*D+tid]; a3 += Wfuse[(D+k+3)*D+tid];
        }
        g_s1[tid]=(a0+a1)+(a2+a3);
    } else if (bid == 469) {
        sh[tid]=bfuse[tid]; __syncthreads();
        float a0=0.f,a1=0.f,a2=0.f,a3=0.f;
        #pragma unroll
        for (int k=0;k<D;k+=4){
            a0 += sh[k+0]*Wabs[(k+0)*D+tid]; a1 += sh[k+1]*Wabs[(k+1)*D+tid];
            a2 += sh[k+2]*Wabs[(k+2)*D+tid]; a3 += sh[k+3]*Wabs[(k+3)*D+tid];
        }
        g_bA[tid] = (a0+a1)+(a2+a3) + babs[tid];
    } else if (bid == 470) {
        sh[tid]=bfuse[tid]; __syncthreads();
        float a0=0.f,a1=0.f,a2=0.f,a3=0.f;
        #pragma unroll
        for (int k=0;k<D;k+=4){
            a0 += sh[k+0]*Wfor[(2*D+k+0)*D+tid]; a1 += sh[k+1]*Wfor[(2*D+k+1)*D+tid];
            a2 += sh[k+2]*Wfor[(2*D+k+2)*D+tid]; a3 += sh[k+3]*Wfor[(2*D+k+3)*D+tid];
        }
        g_bF[tid] = (a0+a1)+(a2+a3) + bfor[tid];
    } else if (bid < 475) {
        int c = (bid-471)*128 + tid;
        if (c < NC){
            float s=0.f;
            #pragma unroll
            for (int dd=0; dd<D; dd+=4){
                float4 e = *(const float4*)&EC[c*D+dd];
                s += e.x*e.x + e.y*e.y + e.z*e.z + e.w*e.w;
            }
            g_rnC[c] = 1.f/fmaxf(sqrtf(s), 1e-8f);
        }
    } else {
        int q = (bid-475)*128 + tid;
        if (q < NQ) g_qd[q] = 10.f/(1.f+__expf(-EQd[q]));
    }
}

// ---------------- prepB: P1/P2 question tables + qdm, plus v1/v2 ----------------
#define NBQ 148
#define QPB 68
#define SMEM_B ((2*D*D + 4*D) * (int)sizeof(float))

__global__ void __launch_bounds__(256) prepB_kernel(
    const float* __restrict__ EQ, const float* __restrict__ EC,
    const int* __restrict__ q2c, const int* __restrict__ q2cm,
    const float* __restrict__ Wabs, const float* __restrict__ Wfor)
{
    const int tid = threadIdx.x;
    const int bid = blockIdx.x;

    if (bid >= NBQ){                       // v1 / v2 blocks (need g_s1 from prepA)
        __shared__ float s1s[D];
        if (tid < D) s1s[tid] = g_s1[tid];
        __syncthreads();
        if (tid < D){
            const float* Wb = (bid==NBQ) ? Wabs : (Wfor + 2*D*D);
            float a0=0.f,a1=0.f,a2=0.f,a3=0.f;
            #pragma unroll
            for (int jj=0;jj<D;jj+=4){
                a0 += s1s[jj+0]*Wb[(jj+0)*D+tid]; a1 += s1s[jj+1]*Wb[(jj+1)*D+tid];
                a2 += s1s[jj+2]*Wb[(jj+2)*D+tid]; a3 += s1s[jj+3]*Wb[(jj+3)*D+tid];
            }
            float a = (a0+a1)+(a2+a3);
            if (bid==NBQ) g_v1[tid]=a; else g_v2[tid]=a;
        }
        return;
    }

    extern __shared__ float smem[];
    float* M1s = smem;            // D*D
    float* M2s = smem + D*D;      // D*D
    float* E4  = smem + 2*D*D;    // 4 questions interleaved: E4[jj*4+q]

    for (int i=tid; i<D*D; i+=256){ M1s[i]=g_M1[i]; M2s[i]=g_M2[i]; }
    __syncthreads();

    const int qbase = bid*QPB;
    for (int gg=0; gg<QPB; gg+=4){
        const int qb = qbase+gg;
        for (int i=tid; i<4*D; i+=256){
            int q = i>>7, jj = i&127;
            int qq = qb+q;
            E4[jj*4+q] = (qq<NQ) ? EQ[qq*D+jj] : 0.f;
        }
        __syncthreads();
        {
            const int halfp = tid>>7, jj = tid&127;
            const float* Ms = halfp ? M2s : M1s;
            float a0=0.f,a1=0.f,a2=0.f,a3=0.f;
            const float4* Ev = (const float4*)E4;
            #pragma unroll 8
            for (int jk=0; jk<D; jk++){
                float4 e = Ev[jk];
                float m = Ms[jk*D+jj];
                a0 += e.x*m; a1 += e.y*m; a2 += e.z*m; a3 += e.w*m;
            }
            float* P = halfp ? g_P2 : g_P1;
            if (qb+0<NQ) P[(qb+0)*D+jj]=a0;
            if (qb+1<NQ) P[(qb+1)*D+jj]=a1;
            if (qb+2<NQ) P[(qb+2)*D+jj]=a2;
            if (qb+3<NQ) P[(qb+3)*D+jj]=a3;
        }
        {   // qdm for the 4 questions, warps 0..3
            const int w = tid>>5, lane = tid&31;
            if (w<4 && (qb+w)<NQ){
                const int q = qb+w;
                int4 cid = ((const int4*)q2c)[q];
                float nrm=0.f,d0=0.f,d1=0.f,d2=0.f,d3=0.f;
                #pragma unroll
                for (int r=0;r<4;r++){
                    int jj = lane + 32*r;
                    float e = E4[jj*4+w];
                    nrm += e*e;
                    d0 += e*EC[cid.x*D+jj];
                    d1 += e*EC[cid.y*D+jj];
                    d2 += e*EC[cid.z*D+jj];
                    d3 += e*EC[cid.w*D+jj];
                }
                #pragma unroll
                for (int off=16; off; off>>=1){
                    nrm += __shfl_down_sync(0xffffffffu, nrm, off);
                    d0  += __shfl_down_sync(0xffffffffu, d0, off);
                    d1  += __shfl_down_sync(0xffffffffu, d1, off);
                    d2  += __shfl_down_sync(0xffffffffu, d2, off);
                    d3  += __shfl_down_sync(0xffffffffu, d3, off);
                }
                if (lane==0){
                    float rq = 1.f/fmaxf(sqrtf(nrm), 1e-8f);
                    int4 mm = ((const int4*)q2cm)[q];
                    float qdm =
                        0.5f*(d0*rq*g_rnC[cid.x]+1.f)*(float)mm.x +
                        0.5f*(d1*rq*g_rnC[cid.y]+1.f)*(float)mm.y +
                        0.5f*(d2*rq*g_rnC[cid.z]+1.f)*(float)mm.z +
                        0.5f*(d3*rq*g_rnC[cid.w]+1.f)*(float)mm.w;
                    g_qdm[q]=qdm;
                }
            }
        }
        __syncthreads();
    }
}

// ---------------- scan: one CTA per batch row; paired-lane matvec, 1 barrier/step ----------------
#define SCAN_THREADS 320   // warps 0..7 matvec (pairs), warps 8..9 output

__global__ void __launch_bounds__(SCAN_THREADS,1) scan_kernel(
    const int* __restrict__ qseq, const int* __restrict__ haseq,
    const int* __restrict__ cseq, const int* __restrict__ itseq,
    const int* __restrict__ utseq,
    const int* __restrict__ q2c, const int* __restrict__ q2cm,
    const float* __restrict__ EC, const float* __restrict__ Wfor,
    const float* __restrict__ lat0, float* __restrict__ out)
{
    __shared__ __align__(16) float lring[4][D];   // slot t&3 holds lc_t; slot 3 init = latent0
    __shared__ int sq[S], sha[S], sc[S], sit[S], sut[S];

    const int b    = blockIdx.x;
    const int tid  = threadIdx.x;
    const int lane = tid & 31;
    const bool ow  = (tid >= 256);

    for (int i=tid; i<S; i+=SCAN_THREADS){
        sq[i]=qseq[b*S+i]; sha[i]=haseq[b*S+i]; sc[i]=cseq[b*S+i];
        sit[i]=itseq[b*S+i]; sut[i]=utseq[b*S+i];
    }
    if (tid < D) lring[3][tid] = lat0[b*D+tid];

    // matvec thread state: column j = tid>>1, k-half sub = tid&1
    int j=0, sub=0;
    float rv1=0.f, rv2=0.f, rbA=0.f, rbF=0.f;
    unsigned long long w2[32];
    if (!ow){
        j = tid >> 1; sub = tid & 1;
        #pragma unroll
        for (int kk=0; kk<32; kk++){
            int k0 = sub*64 + 2*kk;
            unsigned lo = __float_as_uint(Wfor[(k0  )*D + j]);
            unsigned hi = __float_as_uint(Wfor[(k0+1)*D + j]);
            w2[kk] = ((unsigned long long)hi << 32) | lo;
        }
        if (sub==0){ rv1=g_v1[j]; rv2=g_v2[j]; rbA=g_bA[j]; rbF=g_bF[j]; }
    }
    __syncthreads();

    // output-warp state (each of warps 8,9 owns alternating outputs)
    const int ow_idx = (tid>>5) - 8;   // 0 or 1 for output warps
    float E[16];
    float rn0=0,rn1=0,rn2=0,rn3=0, qdv=0, qdmv=0, m0=0,m1=0,m2=0,m3=0;

    for (int t=0; t<S-1; t++){
        if (!ow){
            const float* lprev = lring[(t+3)&3];
            float a_p1=0.f,a_p2=0.f,a_ut=0.f,a_ha=0.f,a_it=0.f,ctv=0.f,lpj=0.f;
            if (sub==0){
                int qt = sq[t]; ctv = (float)sc[t];
                a_p1 = g_P1[qt*D+j];
                a_p2 = g_P2[qt*D+j];
                a_ut = g_UT[sut[t]*D+j];
                a_ha = g_HA[sha[t]*D+j];
                a_it = g_IT[sit[t]*D+j];
                lpj  = lprev[j];
            }
            // matvec partial over this thread's 64-k half (packed f32x2)
            const ulonglong2* xp = (const ulonglong2*)(lprev + sub*64);
            unsigned long long acc0=0ull, acc1=0ull, acc2=0ull, acc3=0ull;
            #pragma unroll
            for (int kk=0; kk<16; kk+=2){
                ulonglong2 v0 = xp[kk];
                ulonglong2 v1 = xp[kk+1];
                ffma2(acc0, v0.x, w2[2*kk  ]);
                ffma2(acc1, v0.y, w2[2*kk+1]);
                ffma2(acc2, v1.x, w2[2*kk+2]);
                ffma2(acc3, v1.y, w2[2*kk+3]);
            }
            float s = ((ulo(acc0)+uhi(acc0)) + (ulo(acc1)+uhi(acc1)))
                    + ((ulo(acc2)+uhi(acc2)) + (ulo(acc3)+uhi(acc3)));
            s += __shfl_xor_sync(0xffffffffu, s, 1);   // combine the two k-halves
            if (sub==0){
                float avec = a_p1 + ctv*rv1 + a_ut + a_ha + rbA;
                float z    = s + a_p2 + ctv*rv2 + a_it + rbF;
                float f    = 1.f/(1.f+__expf(-z));
                lring[t&3][j] = lpj*f + avec;
            }
        } else {
            if ((t&1) == ow_idx){
                // issue loads for output t (concepts of q[t+1]; scalars of q[t])
                int q1 = sq[t+1];
                int4 cid = __ldg((const int4*)q2c + q1);
                const float* e0 = EC + cid.x*D + lane;
                const float* e1 = EC + cid.y*D + lane;
                const float* e2 = EC + cid.z*D + lane;
                const float* e3 = EC + cid.w*D + lane;
                E[0]=e0[0];  E[1]=e0[32];  E[2]=e0[64];  E[3]=e0[96];
                E[4]=e1[0];  E[5]=e1[32];  E[6]=e1[64];  E[7]=e1[96];
                E[8]=e2[0];  E[9]=e2[32];  E[10]=e2[64]; E[11]=e2[96];
                E[12]=e3[0]; E[13]=e3[32]; E[14]=e3[64]; E[15]=e3[96];
                if (lane==0){
                    rn0=g_rnC[cid.x]; rn1=g_rnC[cid.y]; rn2=g_rnC[cid.z]; rn3=g_rnC[cid.w];
                    qdv=g_qd[q1];
                    int qt = sq[t]; qdmv=g_qdm[qt];
                    int4 mm = __ldg((const int4*)q2cm + qt);
                    m0=(float)mm.x; m1=(float)mm.y; m2=(float)mm.z; m3=(float)mm.w;
                }
            } else if (t >= 1){
                // compute output t-1 (this warp loaded its data at iteration t-1)
                const float* lcv = lring[(t-1)&3];
                float x0=lcv[lane], x1=lcv[lane+32], x2=lcv[lane+64], x3=lcv[lane+96];
                float d0 = x0*E[0]  + x1*E[1]  + x2*E[2]  + x3*E[3];
                float d1 = x0*E[4]  + x1*E[5]  + x2*E[6]  + x3*E[7];
                float d2 = x0*E[8]  + x1*E[9]  + x2*E[10] + x3*E[11];
                float d3 = x0*E[12] + x1*E[13] + x2*E[14] + x3*E[15];
                float nv = x0*x0 + x1*x1 + x2*x2 + x3*x3;
                #pragma unroll
                for (int o=16;o;o>>=1){
                    d0 += __shfl_down_sync(0xffffffffu, d0, o);
                    d1 += __shfl_down_sync(0xffffffffu, d1, o);
                    d2 += __shfl_down_sync(0xffffffffu, d2, o);
                    d3 += __shfl_down_sync(0xffffffffu, d3, o);
                    nv += __shfl_down_sync(0xffffffffu, nv, o);
                }
                if (lane==0){
                    float rl = 1.f/fmaxf(sqrtf(nv), 1e-8f);
                    float ss = 0.5f*((d0*rn0*rl+1.f)*m0 + (d1*rn1*rl+1.f)*m1
                                   + (d2*rn2*rl+1.f)*m2 + (d3*rn3*rl+1.f)*m3);
                    float lg = qdv*(ss - qdmv);
                    out[b*S+(t-1)] = 1.f/(1.f+__expf(-lg));
                }
            }
        }
        __syncthreads();
    }

    // epilogue: output S-2 pending on warp with parity (S-2)&1
    if (ow && ow_idx == ((S-2)&1)){
        const float* lcv = lring[(S-2)&3];
        float x0=lcv[lane], x1=lcv[lane+32], x2=lcv[lane+64], x3=lcv[lane+96];
        float d0 = x0*E[0]  + x1*E[1]  + x2*E[2]  + x3*E[3];
        float d1 = x0*E[4]  + x1*E[5]  + x2*E[6]  + x3*E[7];
        float d2 = x0*E[8]  + x1*E[9]  + x2*E[10] + x3*E[11];
        float d3 = x0*E[12] + x1*E[13] + x2*E[14] + x3*E[15];
        float nv = x0*x0 + x1*x1 + x2*x2 + x3*x3;
        #pragma unroll
        for (int o=16;o;o>>=1){
            d0 += __shfl_down_sync(0xffffffffu, d0, o);
            d1 += __shfl_down_sync(0xffffffffu, d1, o);
            d2 += __shfl_down_sync(0xffffffffu, d2, o);
            d3 += __shfl_down_sync(0xffffffffu, d3, o);
            nv += __shfl_down_sync(0xffffffffu, nv, o);
        }
        if (lane==0){
            float rl = 1.f/fmaxf(sqrtf(nv), 1e-8f);
            float ss = 0.5f*((d0*rn0*rl+1.f)*m0 + (d1*rn1*rl+1.f)*m1
                           + (d2*rn2*rl+1.f)*m2 + (d3*rn3*rl+1.f)*m3);
            float lg = qdv*(ss - qdmv);
            out[b*S+(S-2)] = 1.f/(1.f+__expf(-lg));
        }
    }
    if (tid==0) out[b*S + (S-1)] = 0.f;
}

extern "C" void kernel_launch(void* const* d_in, const int* in_sizes, int n_in,
                              void* d_out, int out_size)
{
    const int*   qseq  = (const int*)  d_in[0];
    const int*   haseq = (const int*)  d_in[1];
    const int*   cseq  = (const int*)  d_in[2];
    const int*   itseq = (const int*)  d_in[3];
    const int*   utseq = (const int*)  d_in[4];
    const int*   q2c   = (const int*)  d_in[5];
    const int*   q2cm  = (const int*)  d_in[6];
    const float* EQ    = (const float*)d_in[7];
    const float* EQd   = (const float*)d_in[8];
    const float* EC    = (const float*)d_in[9];
    const float* EIT   = (const float*)d_in[10];
    const float* EUT   = (const float*)d_in[11];
    const float* EHA   = (const float*)d_in[12];
    const float* Wfuse = (const float*)d_in[13];
    const float* bfuse = (const float*)d_in[14];
    const float* Wabs  = (const float*)d_in[15];
    const float* babs  = (const float*)d_in[16];
    const float* Wfor  = (const float*)d_in[17];
    const float* bfor  = (const float*)d_in[18];
    const float* lat0  = (const float*)d_in[19];
    float* out = (float*)d_out;

    cudaFuncSetAttribute(prepB_kernel,
                         cudaFuncAttributeMaxDynamicSharedMemorySize, SMEM_B);

    prepA_kernel<<<554, 128>>>(Wfuse, bfuse, Wabs, babs, Wfor, bfor,
                               EQd, EC, EIT, EUT, EHA);
    prepB_kernel<<<NBQ+2, 256, SMEM_B>>>(EQ, EC, q2c, q2cm, Wabs, Wfor);
    scan_kernel<<<B, SCAN_THREADS>>>(qseq, haseq, cseq, itseq, utseq,
                                     q2c, q2cm, EC, Wfor, lat0, out);
}

// round 5
// speedup vs baseline: 1.3598x; 1.0595x over previous
#include <cuda_runtime.h>
#include <math.h>

#define D   128
#define B   128
#define S   200
#define NQ  10000
#define NC  500

// ---------------- scratch tables (device globals; no allocation) ----------------
__device__ float g_M1[D*D];      // W_fuse_top @ W_absorb_top
__device__ float g_M2[D*D];      // W_fuse_top @ W_forget_bot
__device__ float g_UT[100*D];    // embed_use_time @ W_absorb_mid
__device__ float g_HA[12*D];     // embed_hint_attempt @ W_absorb_bot
__device__ float g_IT[100*D];    // embed_interval_time @ W_forget_mid
__device__ float g_s1[D];        // colsum(W_fuse_bot)
__device__ float g_v1[D];        // s1 @ W_absorb_top
__device__ float g_v2[D];        // s1 @ W_forget_bot
__device__ float g_bA[D];        // b_fuse @ W_absorb_top + b_absorb
__device__ float g_bF[D];        // b_fuse @ W_forget_bot + b_forget
__device__ float g_P1[NQ*D];     // embed_question @ M1
__device__ float g_P2[NQ*D];     // embed_question @ M2
__device__ float g_qd[NQ];       // 10*sigmoid(disc)
__device__ float g_qdm[NQ];      // sum_k qdiff_k * mask_k  (per question)
__device__ float g_rnC[NC];      // 1/max(|concept|,eps)

// packed f32x2 fma (sm_100+). d = a*b + d, elementwise on the two fp32 halves.
__device__ __forceinline__ void ffma2(unsigned long long &d,
                                      unsigned long long a, unsigned long long b){
    asm("fma.rn.f32x2 %0, %1, %2, %0;" : "+l"(d) : "l"(a), "l"(b));
}
__device__ __forceinline__ float ulo(unsigned long long v){ return __uint_as_float((unsigned)v); }
__device__ __forceinline__ float uhi(unsigned long long v){ return __uint_as_float((unsigned)(v>>32)); }

// ---------------- prepA: small composite mats + tables ----------------
__global__ void __launch_bounds__(128) prepA_kernel(
    const float* __restrict__ Wfuse, const float* __restrict__ bfuse,
    const float* __restrict__ Wabs,  const float* __restrict__ babs,
    const float* __restrict__ Wfor,  const float* __restrict__ bfor,
    const float* __restrict__ EQd,   const float* __restrict__ EC,
    const float* __restrict__ EIT,   const float* __restrict__ EUT,
    const float* __restrict__ EHA)
{
    __shared__ float sh[D];
    const int tid = threadIdx.x;
    const int bid = blockIdx.x;

    if (bid < 468) {
        const float* vrow; const float* Wb; float* outp;
        if (bid < 128)      { vrow = Wfuse + bid*D;        Wb = Wabs;           outp = g_M1 + bid*D; }
        else if (bid < 256) { vrow = Wfuse + (bid-128)*D;  Wb = Wfor + 2*D*D;   outp = g_M2 + (bid-128)*D; }
        else if (bid < 356) { vrow = EUT + (bid-256)*D;    Wb = Wabs + D*D;     outp = g_UT + (bid-256)*D; }
        else if (bid < 368) { vrow = EHA + (bid-356)*D;    Wb = Wabs + 2*D*D;   outp = g_HA + (bid-356)*D; }
        else                { vrow = EIT + (bid-368)*D;    Wb = Wfor + D*D;     outp = g_IT + (bid-368)*D; }
        sh[tid] = vrow[tid];
        __syncthreads();
        float a0=0.f,a1=0.f,a2=0.f,a3=0.f,a4=0.f,a5=0.f,a6=0.f,a7=0.f;
        #pragma unroll
        for (int jj=0; jj<D; jj+=8){
            a0 += sh[jj+0]*Wb[(jj+0)*D+tid];
            a1 += sh[jj+1]*Wb[(jj+1)*D+tid];
            a2 += sh[jj+2]*Wb[(jj+2)*D+tid];
            a3 += sh[jj+3]*Wb[(jj+3)*D+tid];
            a4 += sh[jj+4]*Wb[(jj+4)*D+tid];
            a5 += sh[jj+5]*Wb[(jj+5)*D+tid];
            a6 += sh[jj+6]*Wb[(jj+6)*D+tid];
            a7 += sh[jj+7]*Wb[(jj+7)*D+tid];
        }
        outp[tid] = ((a0+a1)+(a2+a3))+((a4+a5)+(a6+a7));
    } else if (bid == 468) {
        float a0=0.f,a1=0.f,a2=0.f,a3=0.f;
        #pragma unroll
        for (int k=0;k<D;k+=4){
            a0 += Wfuse[(D+k+0)*D+tid]; a1 += Wfuse[(D+k+1)*D+tid];
            a2 += Wfuse[(D+k+2)*D+tid]; a3 += Wfuse[(D+k+3)*D+tid];
        }
        g_s1[tid]=(a0+a1)+(a2+a3);
    } else if (bid == 469) {
        sh[tid]=bfuse[tid]; __syncthreads();
        float a0=0.f,a1=0.f,a2=0.f,a3=0.f;
        #pragma unroll
        for (int k=0;k<D;k+=4){
            a0 += sh[k+0]*Wabs[(k+0)*D+tid]; a1 += sh[k+1]*Wabs[(k+1)*D+tid];
            a2 += sh[k+2]*Wabs[(k+2)*D+tid]; a3 += sh[k+3]*Wabs[(k+3)*D+tid];
        }
        g_bA[tid] = (a0+a1)+(a2+a3) + babs[tid];
    } else if (bid == 470) {
        sh[tid]=bfuse[tid]; __syncthreads();
        float a0=0.f,a1=0.f,a2=0.f,a3=0.f;
        #pragma unroll
        for (int k=0;k<D;k+=4){
            a0 += sh[k+0]*Wfor[(2*D+k+0)*D+tid]; a1 += sh[k+1]*Wfor[(2*D+k+1)*D+tid];
            a2 += sh[k+2]*Wfor[(2*D+k+2)*D+tid]; a3 += sh[k+3]*Wfor[(2*D+k+3)*D+tid];
        }
        g_bF[tid] = (a0+a1)+(a2+a3) + bfor[tid];
    } else if (bid < 475) {
        int c = (bid-471)*128 + tid;
        if (c < NC){
            float s=0.f;
            #pragma unroll
            for (int dd=0; dd<D; dd+=4){
                float4 e = *(const float4*)&EC[c*D+dd];
                s += e.x*e.x + e.y*e.y + e.z*e.z + e.w*e.w;
            }
            g_rnC[c] = 1.f/fmaxf(sqrtf(s), 1e-8f);
        }
    } else {
        int q = (bid-475)*128 + tid;
        if (q < NQ) g_qd[q] = 10.f/(1.f+__expf(-EQd[q]));
    }
}

// ---------------- prepB: P1/P2 question tables + qdm, plus v1/v2 ----------------
#define NBQ 148
#define QPB 68
#define SMEM_B ((2*D*D + 4*D) * (int)sizeof(float))

__global__ void __launch_bounds__(256) prepB_kernel(
    const float* __restrict__ EQ, const float* __restrict__ EC,
    const int* __restrict__ q2c, const int* __restrict__ q2cm,
    const float* __restrict__ Wabs, const float* __restrict__ Wfor)
{
    const int tid = threadIdx.x;
    const int bid = blockIdx.x;

    if (bid >= NBQ){                       // v1 / v2 blocks (need g_s1 from prepA)
        __shared__ float s1s[D];
        if (tid < D) s1s[tid] = g_s1[tid];
        __syncthreads();
        if (tid < D){
            const float* Wb = (bid==NBQ) ? Wabs : (Wfor + 2*D*D);
            float a0=0.f,a1=0.f,a2=0.f,a3=0.f;
            #pragma unroll
            for (int jj=0;jj<D;jj+=4){
                a0 += s1s[jj+0]*Wb[(jj+0)*D+tid]; a1 += s1s[jj+1]*Wb[(jj+1)*D+tid];
                a2 += s1s[jj+2]*Wb[(jj+2)*D+tid]; a3 += s1s[jj+3]*Wb[(jj+3)*D+tid];
            }
            float a = (a0+a1)+(a2+a3);
            if (bid==NBQ) g_v1[tid]=a; else g_v2[tid]=a;
        }
        return;
    }

    extern __shared__ float smem[];
    float* M1s = smem;            // D*D
    float* M2s = smem + D*D;      // D*D
    float* E4  = smem + 2*D*D;    // 4 questions interleaved: E4[jj*4+q]

    for (int i=tid; i<D*D; i+=256){ M1s[i]=g_M1[i]; M2s[i]=g_M2[i]; }
    __syncthreads();

    const int qbase = bid*QPB;
    for (int gg=0; gg<QPB; gg+=4){
        const int qb = qbase+gg;
        for (int i=tid; i<4*D; i+=256){
            int q = i>>7, jj = i&127;
            int qq = qb+q;
            E4[jj*4+q] = (qq<NQ) ? EQ[qq*D+jj] : 0.f;
        }
        __syncthreads();
        {
            const int halfp = tid>>7, jj = tid&127;
            const float* Ms = halfp ? M2s : M1s;
            float a0=0.f,a1=0.f,a2=0.f,a3=0.f;
            const float4* Ev = (const float4*)E4;
            #pragma unroll 8
            for (int jk=0; jk<D; jk++){
                float4 e = Ev[jk];
                float m = Ms[jk*D+jj];
                a0 += e.x*m; a1 += e.y*m; a2 += e.z*m; a3 += e.w*m;
            }
            float* P = halfp ? g_P2 : g_P1;
            if (qb+0<NQ) P[(qb+0)*D+jj]=a0;
            if (qb+1<NQ) P[(qb+1)*D+jj]=a1;
            if (qb+2<NQ) P[(qb+2)*D+jj]=a2;
            if (qb+3<NQ) P[(qb+3)*D+jj]=a3;
        }
        {   // qdm for the 4 questions, warps 0..3
            const int w = tid>>5, lane = tid&31;
            if (w<4 && (qb+w)<NQ){
                const int q = qb+w;
                int4 cid = ((const int4*)q2c)[q];
                float nrm=0.f,d0=0.f,d1=0.f,d2=0.f,d3=0.f;
                #pragma unroll
                for (int r=0;r<4;r++){
                    int jj = lane + 32*r;
                    float e = E4[jj*4+w];
                    nrm += e*e;
                    d0 += e*EC[cid.x*D+jj];
                    d1 += e*EC[cid.y*D+jj];
                    d2 += e*EC[cid.z*D+jj];
                    d3 += e*EC[cid.w*D+jj];
                }
                #pragma unroll
                for (int off=16; off; off>>=1){
                    nrm += __shfl_down_sync(0xffffffffu, nrm, off);
                    d0  += __shfl_down_sync(0xffffffffu, d0, off);
                    d1  += __shfl_down_sync(0xffffffffu, d1, off);
                    d2  += __shfl_down_sync(0xffffffffu, d2, off);
                    d3  += __shfl_down_sync(0xffffffffu, d3, off);
                }
                if (lane==0){
                    float rq = 1.f/fmaxf(sqrtf(nrm), 1e-8f);
                    int4 mm = ((const int4*)q2cm)[q];
                    float qdm =
                        0.5f*(d0*rq*g_rnC[cid.x]+1.f)*(float)mm.x +
                        0.5f*(d1*rq*g_rnC[cid.y]+1.f)*(float)mm.y +
                        0.5f*(d2*rq*g_rnC[cid.z]+1.f)*(float)mm.z +
                        0.5f*(d3*rq*g_rnC[cid.w]+1.f)*(float)mm.w;
                    g_qdm[q]=qdm;
                }
            }
        }
        __syncthreads();
    }
}

// ---------------- scan: one CTA per batch row; deep-prefetch pipeline ----------------
#define SCAN_THREADS 320   // warps 0..7 matvec (lane pairs), warps 8..9 output

// issue concept/scalar loads for output "o" into register set suffix SFX
#define OW_LOAD_SET(SFX, o) do{                                                          \
    int q1_ = sq[(o)+1];                                                                 \
    int4 cid_ = __ldg((const int4*)q2c + q1_);                                           \
    const float* e0_ = EC + cid_.x*D + lane;                                             \
    const float* e1_ = EC + cid_.y*D + lane;                                             \
    const float* e2_ = EC + cid_.z*D + lane;                                             \
    const float* e3_ = EC + cid_.w*D + lane;                                             \
    E##SFX[0]=e0_[0];  E##SFX[1]=e0_[32];  E##SFX[2]=e0_[64];  E##SFX[3]=e0_[96];        \
    E##SFX[4]=e1_[0];  E##SFX[5]=e1_[32];  E##SFX[6]=e1_[64];  E##SFX[7]=e1_[96];        \
    E##SFX[8]=e2_[0];  E##SFX[9]=e2_[32];  E##SFX[10]=e2_[64]; E##SFX[11]=e2_[96];       \
    E##SFX[12]=e3_[0]; E##SFX[13]=e3_[32]; E##SFX[14]=e3_[64]; E##SFX[15]=e3_[96];       \
    if (lane==0){                                                                        \
        rn0##SFX=g_rnC[cid_.x]; rn1##SFX=g_rnC[cid_.y];                                  \
        rn2##SFX=g_rnC[cid_.z]; rn3##SFX=g_rnC[cid_.w];                                  \
        qd##SFX=g_qd[q1_];                                                               \
        int qt_ = sq[o]; qdm##SFX=g_qdm[qt_];                                            \
        int4 mm_ = __ldg((const int4*)q2cm + qt_);                                       \
        m0##SFX=(float)mm_.x; m1##SFX=(float)mm_.y;                                      \
        m2##SFX=(float)mm_.z; m3##SFX=(float)mm_.w;                                      \
    }                                                                                    \
}while(0)

// dots + tail for output "o" using register set SFX; lc vector in shared
#define OW_EMIT_SET(SFX, o) do{                                                          \
    const float* lcv_ = lring[(o)&3];                                                    \
    float x0_=lcv_[lane], x1_=lcv_[lane+32], x2_=lcv_[lane+64], x3_=lcv_[lane+96];       \
    float d0_ = x0_*E##SFX[0]  + x1_*E##SFX[1]  + x2_*E##SFX[2]  + x3_*E##SFX[3];        \
    float d1_ = x0_*E##SFX[4]  + x1_*E##SFX[5]  + x2_*E##SFX[6]  + x3_*E##SFX[7];        \
    float d2_ = x0_*E##SFX[8]  + x1_*E##SFX[9]  + x2_*E##SFX[10] + x3_*E##SFX[11];       \
    float d3_ = x0_*E##SFX[12] + x1_*E##SFX[13] + x2_*E##SFX[14] + x3_*E##SFX[15];       \
    float nv_ = x0_*x0_ + x1_*x1_ + x2_*x2_ + x3_*x3_;                                   \
    _Pragma("unroll")                                                                    \
    for (int o_=16;o_;o_>>=1){                                                           \
        d0_ += __shfl_down_sync(0xffffffffu, d0_, o_);                                   \
        d1_ += __shfl_down_sync(0xffffffffu, d1_, o_);                                   \
        d2_ += __shfl_down_sync(0xffffffffu, d2_, o_);                                   \
        d3_ += __shfl_down_sync(0xffffffffu, d3_, o_);                                   \
        nv_ += __shfl_down_sync(0xffffffffu, nv_, o_);                                   \
    }                                                                                    \
    if (lane==0){                                                                        \
        float rl_ = 1.f/fmaxf(sqrtf(nv_), 1e-8f);                                        \
        float ss_ = 0.5f*((d0_*rn0##SFX*rl_+1.f)*m0##SFX + (d1_*rn1##SFX*rl_+1.f)*m1##SFX\
                        + (d2_*rn2##SFX*rl_+1.f)*m2##SFX + (d3_*rn3##SFX*rl_+1.f)*m3##SFX);\
        float lg_ = qd##SFX*(ss_ - qdm##SFX);                                            \
        out[b*S+(o)] = 1.f/(1.f+__expf(-lg_));                                           \
    }                                                                                    \
}while(0)

__global__ void __launch_bounds__(SCAN_THREADS,1) scan_kernel(
    const int* __restrict__ qseq, const int* __restrict__ haseq,
    const int* __restrict__ cseq, const int* __restrict__ itseq,
    const int* __restrict__ utseq,
    const int* __restrict__ q2c, const int* __restrict__ q2cm,
    const float* __restrict__ EC, const float* __restrict__ Wfor,
    const float* __restrict__ lat0, float* __restrict__ out)
{
    __shared__ __align__(16) float lring[4][D];   // slot t&3 holds lc_t; slot 3 = latent0
    __shared__ int sq[S], sha[S], sc[S], sit[S], sut[S];

    const int b    = blockIdx.x;
    const int tid  = threadIdx.x;
    const int lane = tid & 31;
    const bool ow  = (tid >= 256);

    for (int i=tid; i<S; i+=SCAN_THREADS){
        sq[i]=qseq[b*S+i]; sha[i]=haseq[b*S+i]; sc[i]=cseq[b*S+i];
        sit[i]=itseq[b*S+i]; sut[i]=utseq[b*S+i];
    }
    if (tid < D) lring[3][tid] = lat0[b*D+tid];

    // matvec thread state: column j = tid>>1, k-half sub = tid&1
    int j=0, sub=0;
    float rv1=0.f, rv2=0.f, rbA=0.f, rbF=0.f;
    unsigned long long w2[32];
    if (!ow){
        j = tid >> 1; sub = tid & 1;
        #pragma unroll
        for (int kk=0; kk<32; kk++){
            int k0 = sub*64 + 2*kk;
            unsigned lo = __float_as_uint(Wfor[(k0  )*D + j]);
            unsigned hi = __float_as_uint(Wfor[(k0+1)*D + j]);
            w2[kk] = ((unsigned long long)hi << 32) | lo;
        }
        if (sub==0){ rv1=g_v1[j]; rv2=g_v2[j]; rbA=g_bA[j]; rbF=g_bF[j]; }
    }
    __syncthreads();   // seq arrays + lring[3] visible

    // matvec prefetch registers (cur = step t, nxt = step t+1)
    float cP1=0,cP2=0,cUT=0,cHA=0,cIT=0;
    if (!ow && sub==0){
        int q0 = sq[0];
        cP1 = g_P1[q0*D+j]; cP2 = g_P2[q0*D+j];
        cUT = g_UT[sut[0]*D+j]; cHA = g_HA[sha[0]*D+j]; cIT = g_IT[sit[0]*D+j];
    }

    // output-warp state: warp p owns outputs o with o%2==p; double-buffered sets A/B,
    // set for output o is (o>>1)&1  (0->A, 1->B)
    const int p = (tid>>5) - 8;
    float EA[16], EB[16];
    float rn0A=0,rn1A=0,rn2A=0,rn3A=0,qdA=0,qdmA=0,m0A=0,m1A=0,m2A=0,m3A=0;
    float rn0B=0,rn1B=0,rn2B=0,rn3B=0,qdB=0,qdmB=0,m0B=0,m1B=0,m2B=0,m3B=0;
    if (ow){
        OW_LOAD_SET(A, p);       // outputs 0 and 1 -> set A of each warp
    }

    for (int t=0; t<S-1; t++){
        if (!ow){
            // prefetch tables for step t+1 (indices always in-bounds: sq[t+1] valid for t+1<=199)
            float nP1=0,nP2=0,nUT=0,nHA=0,nIT=0;
            if (sub==0){
                int q1 = sq[t+1];
                nP1 = __ldg(&g_P1[q1*D+j]);  nP2 = __ldg(&g_P2[q1*D+j]);
                nUT = __ldg(&g_UT[sut[t+1]*D+j]);
                nHA = __ldg(&g_HA[sha[t+1]*D+j]);
                nIT = __ldg(&g_IT[sit[t+1]*D+j]);
            }
            const float* lprev = lring[(t+3)&3];
            float lpj = (sub==0) ? lprev[j] : 0.f;
            // matvec partial over this thread's 64-k half (packed f32x2)
            const ulonglong2* xp = (const ulonglong2*)(lprev + sub*64);
            unsigned long long acc0=0ull, acc1=0ull, acc2=0ull, acc3=0ull;
            #pragma unroll
            for (int kk=0; kk<16; kk+=2){
                ulonglong2 v0 = xp[kk];
                ulonglong2 v1 = xp[kk+1];
                ffma2(acc0, v0.x, w2[2*kk  ]);
                ffma2(acc1, v0.y, w2[2*kk+1]);
                ffma2(acc2, v1.x, w2[2*kk+2]);
                ffma2(acc3, v1.y, w2[2*kk+3]);
            }
            float s = ((ulo(acc0)+uhi(acc0)) + (ulo(acc1)+uhi(acc1)))
                    + ((ulo(acc2)+uhi(acc2)) + (ulo(acc3)+uhi(acc3)));
            s += __shfl_xor_sync(0xffffffffu, s, 1);   // combine the two k-halves
            if (sub==0){
                float ctv  = (float)sc[t];
                float avec = cP1 + ctv*rv1 + cUT + cHA + rbA;
                float z    = s + cP2 + ctv*rv2 + cIT + rbF;
                float f    = 1.f/(1.f+__expf(-z));
                lring[t&3][j] = lpj*f + avec;
                cP1=nP1; cP2=nP2; cUT=nUT; cHA=nHA; cIT=nIT;
            }
        } else {
            if ((t&1) == p){
                // issue loads for output t+2 (3 iterations of slack)
                if (t+2 <= S-2){
                    if ((((t+2)>>1)&1)==0) OW_LOAD_SET(A, t+2);
                    else                   OW_LOAD_SET(B, t+2);
                }
            } else if (t >= 1){
                // emit output t-1 (its set was loaded 3 iterations ago)
                int o = t-1;
                if (((o>>1)&1)==0) OW_EMIT_SET(A, o);
                else               OW_EMIT_SET(B, o);
            }
        }
        __syncthreads();
    }

    // epilogue: output S-2 = 198 belongs to warp p=0, set ((198>>1)&1)=1 -> B
    if (ow && p == ((S-2)&1)){
        if ((((S-2)>>1)&1)==0) OW_EMIT_SET(A, S-2);
        else                   OW_EMIT_SET(B, S-2);
    }
    if (tid==0) out[b*S + (S-1)] = 0.f;
}

extern "C" void kernel_launch(void* const* d_in, const int* in_sizes, int n_in,
                              void* d_out, int out_size)
{
    const int*   qseq  = (const int*)  d_in[0];
    const int*   haseq = (const int*)  d_in[1];
    const int*   cseq  = (const int*)  d_in[2];
    const int*   itseq = (const int*)  d_in[3];
    const int*   utseq = (const int*)  d_in[4];
    const int*   q2c   = (const int*)  d_in[5];
    const int*   q2cm  = (const int*)  d_in[6];
    const float* EQ    = (const float*)d_in[7];
    const float* EQd   = (const float*)d_in[8];
    const float* EC    = (const float*)d_in[9];
    const float* EIT   = (const float*)d_in[10];
    const float* EUT   = (const float*)d_in[11];
    const float* EHA   = (const float*)d_in[12];
    const float* Wfuse = (const float*)d_in[13];
    const float* bfuse = (const float*)d_in[14];
    const float* Wabs  = (const float*)d_in[15];
    const float* babs  = (const float*)d_in[16];
    const float* Wfor  = (const float*)d_in[17];
    const float* bfor  = (const float*)d_in[18];
    const float* lat0  = (const float*)d_in[19];
    float* out = (float*)d_out;

    cudaFuncSetAttribute(prepB_kernel,
                         cudaFuncAttributeMaxDynamicSharedMemorySize, SMEM_B);

    prepA_kernel<<<554, 128>>>(Wfuse, bfuse, Wabs, babs, Wfor, bfor,
                               EQd, EC, EIT, EUT, EHA);
    prepB_kernel<<<NBQ+2, 256, SMEM_B>>>(EQ, EC, q2c, q2cm, Wabs, Wfor);
    scan_kernel<<<B, SCAN_THREADS>>>(qseq, haseq, cseq, itseq, utseq,
                                     q2c, q2cm, EC, Wfor, lat0, out);
}

// round 6
// speedup vs baseline: 1.6622x; 1.2224x over previous
#include <cuda_runtime.h>
#include <math.h>

#define D   128
#define B   128
#define S   200
#define NQ  10000
#define NC  500

// ---------------- scratch tables (device globals; no allocation) ----------------
__device__ float g_M1[D*D];      // W_fuse_top @ W_absorb_top
__device__ float g_M2[D*D];      // W_fuse_top @ W_forget_bot
__device__ float g_UT[100*D];    // embed_use_time @ W_absorb_mid
__device__ float g_HA[12*D];     // embed_hint_attempt @ W_absorb_bot
__device__ float g_IT[100*D];    // embed_interval_time @ W_forget_mid
__device__ float g_s1[D];        // colsum(W_fuse_bot)
__device__ float g_v1[D];        // s1 @ W_absorb_top
__device__ float g_v2[D];        // s1 @ W_forget_bot
__device__ float g_bA[D];        // b_fuse @ W_absorb_top + b_absorb
__device__ float g_bF[D];        // b_fuse @ W_forget_bot + b_forget
__device__ float g_P1[NQ*D];     // embed_question @ M1
__device__ float g_P2[NQ*D];     // embed_question @ M2
__device__ float g_qd[NQ];       // 10*sigmoid(disc)
__device__ float g_qdm[NQ];      // sum_k qdiff_k * mask_k  (per question)
__device__ float g_rnC[NC];      // 1/max(|concept|,eps)

// packed f32x2 ops (sm_100+)
__device__ __forceinline__ void ffma2(unsigned long long &d,
                                      unsigned long long a, unsigned long long b){
    asm("fma.rn.f32x2 %0, %1, %2, %0;" : "+l"(d) : "l"(a), "l"(b));
}
__device__ __forceinline__ void fadd2(unsigned long long &d, unsigned long long a){
    asm("add.rn.f32x2 %0, %0, %1;" : "+l"(d) : "l"(a));
}
__device__ __forceinline__ float ulo(unsigned long long v){ return __uint_as_float((unsigned)v); }
__device__ __forceinline__ float uhi(unsigned long long v){ return __uint_as_float((unsigned)(v>>32)); }

// ---------------- prepA: small composite mats + tables ----------------
__global__ void __launch_bounds__(128) prepA_kernel(
    const float* __restrict__ Wfuse, const float* __restrict__ bfuse,
    const float* __restrict__ Wabs,  const float* __restrict__ babs,
    const float* __restrict__ Wfor,  const float* __restrict__ bfor,
    const float* __restrict__ EQd,   const float* __restrict__ EC,
    const float* __restrict__ EIT,   const float* __restrict__ EUT,
    const float* __restrict__ EHA)
{
    __shared__ float sh[D];
    const int tid = threadIdx.x;
    const int bid = blockIdx.x;

    if (bid < 468) {
        const float* vrow; const float* Wb; float* outp;
        if (bid < 128)      { vrow = Wfuse + bid*D;        Wb = Wabs;           outp = g_M1 + bid*D; }
        else if (bid < 256) { vrow = Wfuse + (bid-128)*D;  Wb = Wfor + 2*D*D;   outp = g_M2 + (bid-128)*D; }
        else if (bid < 356) { vrow = EUT + (bid-256)*D;    Wb = Wabs + D*D;     outp = g_UT + (bid-256)*D; }
        else if (bid < 368) { vrow = EHA + (bid-356)*D;    Wb = Wabs + 2*D*D;   outp = g_HA + (bid-356)*D; }
        else                { vrow = EIT + (bid-368)*D;    Wb = Wfor + D*D;     outp = g_IT + (bid-368)*D; }
        sh[tid] = vrow[tid];
        __syncthreads();
        float a0=0.f,a1=0.f,a2=0.f,a3=0.f,a4=0.f,a5=0.f,a6=0.f,a7=0.f;
        #pragma unroll
        for (int jj=0; jj<D; jj+=8){
            a0 += sh[jj+0]*Wb[(jj+0)*D+tid];
            a1 += sh[jj+1]*Wb[(jj+1)*D+tid];
            a2 += sh[jj+2]*Wb[(jj+2)*D+tid];
            a3 += sh[jj+3]*Wb[(jj+3)*D+tid];
            a4 += sh[jj+4]*Wb[(jj+4)*D+tid];
            a5 += sh[jj+5]*Wb[(jj+5)*D+tid];
            a6 += sh[jj+6]*Wb[(jj+6)*D+tid];
            a7 += sh[jj+7]*Wb[(jj+7)*D+tid];
        }
        outp[tid] = ((a0+a1)+(a2+a3))+((a4+a5)+(a6+a7));
    } else if (bid == 468) {
        float a0=0.f,a1=0.f,a2=0.f,a3=0.f;
        #pragma unroll
        for (int k=0;k<D;k+=4){
            a0 += Wfuse[(D+k+0)*D+tid]; a1 += Wfuse[(D+k+1)*D+tid];
            a2 += Wfuse[(D+k+2)*D+tid]; a3 += Wfuse[(D+k+3)*D+tid];
        }
        g_s1[tid]=(a0+a1)+(a2+a3);
    } else if (bid == 469) {
        sh[tid]=bfuse[tid]; __syncthreads();
        float a0=0.f,a1=0.f,a2=0.f,a3=0.f;
        #pragma unroll
        for (int k=0;k<D;k+=4){
            a0 += sh[k+0]*Wabs[(k+0)*D+tid]; a1 += sh[k+1]*Wabs[(k+1)*D+tid];
            a2 += sh[k+2]*Wabs[(k+2)*D+tid]; a3 += sh[k+3]*Wabs[(k+3)*D+tid];
        }
        g_bA[tid] = (a0+a1)+(a2+a3) + babs[tid];
    } else if (bid == 470) {
        sh[tid]=bfuse[tid]; __syncthreads();
        float a0=0.f,a1=0.f,a2=0.f,a3=0.f;
        #pragma unroll
        for (int k=0;k<D;k+=4){
            a0 += sh[k+0]*Wfor[(2*D+k+0)*D+tid]; a1 += sh[k+1]*Wfor[(2*D+k+1)*D+tid];
            a2 += sh[k+2]*Wfor[(2*D+k+2)*D+tid]; a3 += sh[k+3]*Wfor[(2*D+k+3)*D+tid];
        }
        g_bF[tid] = (a0+a1)+(a2+a3) + bfor[tid];
    } else if (bid < 475) {
        int c = (bid-471)*128 + tid;
        if (c < NC){
            float s=0.f;
            #pragma unroll
            for (int dd=0; dd<D; dd+=4){
                float4 e = *(const float4*)&EC[c*D+dd];
                s += e.x*e.x + e.y*e.y + e.z*e.z + e.w*e.w;
            }
            g_rnC[c] = 1.f/fmaxf(sqrtf(s), 1e-8f);
        }
    } else {
        int q = (bid-475)*128 + tid;
        if (q < NQ) g_qd[q] = 10.f/(1.f+__expf(-EQd[q]));
    }
}

// ---------------- prepB: P1/P2 question tables + qdm, plus v1/v2 ----------------
#define NBQ 148
#define QPB 68
#define SMEM_B ((2*D*D + 4*D) * (int)sizeof(float))

__global__ void __launch_bounds__(256) prepB_kernel(
    const float* __restrict__ EQ, const float* __restrict__ EC,
    const int* __restrict__ q2c, const int* __restrict__ q2cm,
    const float* __restrict__ Wabs, const float* __restrict__ Wfor)
{
    const int tid = threadIdx.x;
    const int bid = blockIdx.x;

    if (bid >= NBQ){                       // v1 / v2 blocks (need g_s1 from prepA)
        __shared__ float s1s[D];
        if (tid < D) s1s[tid] = g_s1[tid];
        __syncthreads();
        if (tid < D){
            const float* Wb = (bid==NBQ) ? Wabs : (Wfor + 2*D*D);
            float a0=0.f,a1=0.f,a2=0.f,a3=0.f;
            #pragma unroll
            for (int jj=0;jj<D;jj+=4){
                a0 += s1s[jj+0]*Wb[(jj+0)*D+tid]; a1 += s1s[jj+1]*Wb[(jj+1)*D+tid];
                a2 += s1s[jj+2]*Wb[(jj+2)*D+tid]; a3 += s1s[jj+3]*Wb[(jj+3)*D+tid];
            }
            float a = (a0+a1)+(a2+a3);
            if (bid==NBQ) g_v1[tid]=a; else g_v2[tid]=a;
        }
        return;
    }

    extern __shared__ float smem[];
    float* M1s = smem;            // D*D
    float* M2s = smem + D*D;      // D*D
    float* E4  = smem + 2*D*D;    // 4 questions interleaved: E4[jj*4+q]

    for (int i=tid; i<D*D; i+=256){ M1s[i]=g_M1[i]; M2s[i]=g_M2[i]; }
    __syncthreads();

    const int qbase = bid*QPB;
    for (int gg=0; gg<QPB; gg+=4){
        const int qb = qbase+gg;
        for (int i=tid; i<4*D; i+=256){
            int q = i>>7, jj = i&127;
            int qq = qb+q;
            E4[jj*4+q] = (qq<NQ) ? EQ[qq*D+jj] : 0.f;
        }
        __syncthreads();
        {
            const int halfp = tid>>7, jj = tid&127;
            const float* Ms = halfp ? M2s : M1s;
            float a0=0.f,a1=0.f,a2=0.f,a3=0.f;
            const float4* Ev = (const float4*)E4;
            #pragma unroll 8
            for (int jk=0; jk<D; jk++){
                float4 e = Ev[jk];
                float m = Ms[jk*D+jj];
                a0 += e.x*m; a1 += e.y*m; a2 += e.z*m; a3 += e.w*m;
            }
            float* P = halfp ? g_P2 : g_P1;
            if (qb+0<NQ) P[(qb+0)*D+jj]=a0;
            if (qb+1<NQ) P[(qb+1)*D+jj]=a1;
            if (qb+2<NQ) P[(qb+2)*D+jj]=a2;
            if (qb+3<NQ) P[(qb+3)*D+jj]=a3;
        }
        {   // qdm for the 4 questions, warps 0..3
            const int w = tid>>5, lane = tid&31;
            if (w<4 && (qb+w)<NQ){
                const int q = qb+w;
                int4 cid = ((const int4*)q2c)[q];
                float nrm=0.f,d0=0.f,d1=0.f,d2=0.f,d3=0.f;
                #pragma unroll
                for (int r=0;r<4;r++){
                    int jj = lane + 32*r;
                    float e = E4[jj*4+w];
                    nrm += e*e;
                    d0 += e*EC[cid.x*D+jj];
                    d1 += e*EC[cid.y*D+jj];
                    d2 += e*EC[cid.z*D+jj];
                    d3 += e*EC[cid.w*D+jj];
                }
                #pragma unroll
                for (int off=16; off; off>>=1){
                    nrm += __shfl_down_sync(0xffffffffu, nrm, off);
                    d0  += __shfl_down_sync(0xffffffffu, d0, off);
                    d1  += __shfl_down_sync(0xffffffffu, d1, off);
                    d2  += __shfl_down_sync(0xffffffffu, d2, off);
                    d3  += __shfl_down_sync(0xffffffffu, d3, off);
                }
                if (lane==0){
                    float rq = 1.f/fmaxf(sqrtf(nrm), 1e-8f);
                    int4 mm = ((const int4*)q2cm)[q];
                    float qdm =
                        0.5f*(d0*rq*g_rnC[cid.x]+1.f)*(float)mm.x +
                        0.5f*(d1*rq*g_rnC[cid.y]+1.f)*(float)mm.y +
                        0.5f*(d2*rq*g_rnC[cid.z]+1.f)*(float)mm.z +
                        0.5f*(d3*rq*g_rnC[cid.w]+1.f)*(float)mm.w;
                    g_qdm[q]=qdm;
                }
            }
        }
        __syncthreads();
    }
}

// ---------------- scan: one CTA per row; thread-local recurrence, split barriers ----------------
#define SCAN_THREADS 192   // warps 0..3 matvec (1 column/thread), warps 4..5 output

#define OW_LOAD_SET(SFX, o) do{                                                          \
    int q1_ = sq[(o)+1];                                                                 \
    int4 cid_ = __ldg((const int4*)q2c + q1_);                                           \
    const float* e0_ = EC + cid_.x*D + lane;                                             \
    const float* e1_ = EC + cid_.y*D + lane;                                             \
    const float* e2_ = EC + cid_.z*D + lane;                                             \
    const float* e3_ = EC + cid_.w*D + lane;                                             \
    E##SFX[0]=e0_[0];  E##SFX[1]=e0_[32];  E##SFX[2]=e0_[64];  E##SFX[3]=e0_[96];        \
    E##SFX[4]=e1_[0];  E##SFX[5]=e1_[32];  E##SFX[6]=e1_[64];  E##SFX[7]=e1_[96];        \
    E##SFX[8]=e2_[0];  E##SFX[9]=e2_[32];  E##SFX[10]=e2_[64]; E##SFX[11]=e2_[96];       \
    E##SFX[12]=e3_[0]; E##SFX[13]=e3_[32]; E##SFX[14]=e3_[64]; E##SFX[15]=e3_[96];       \
    if (lane==0){                                                                        \
        rn0##SFX=g_rnC[cid_.x]; rn1##SFX=g_rnC[cid_.y];                                  \
        rn2##SFX=g_rnC[cid_.z]; rn3##SFX=g_rnC[cid_.w];                                  \
        qd##SFX=g_qd[q1_];                                                               \
        int qt_ = sq[o]; qdm##SFX=g_qdm[qt_];                                            \
        int4 mm_ = __ldg((const int4*)q2cm + qt_);                                       \
        m0##SFX=(float)mm_.x; m1##SFX=(float)mm_.y;                                      \
        m2##SFX=(float)mm_.z; m3##SFX=(float)mm_.w;                                      \
    }                                                                                    \
}while(0)

#define OW_EMIT_SET(SFX, o) do{                                                          \
    const float* lcv_ = lring[(o)&3];                                                    \
    float x0_=lcv_[lane], x1_=lcv_[lane+32], x2_=lcv_[lane+64], x3_=lcv_[lane+96];       \
    float d0_ = x0_*E##SFX[0]  + x1_*E##SFX[1]  + x2_*E##SFX[2]  + x3_*E##SFX[3];        \
    float d1_ = x0_*E##SFX[4]  + x1_*E##SFX[5]  + x2_*E##SFX[6]  + x3_*E##SFX[7];        \
    float d2_ = x0_*E##SFX[8]  + x1_*E##SFX[9]  + x2_*E##SFX[10] + x3_*E##SFX[11];       \
    float d3_ = x0_*E##SFX[12] + x1_*E##SFX[13] + x2_*E##SFX[14] + x3_*E##SFX[15];       \
    float nv_ = x0_*x0_ + x1_*x1_ + x2_*x2_ + x3_*x3_;                                   \
    _Pragma("unroll")                                                                    \
    for (int o_=16;o_;o_>>=1){                                                           \
        d0_ += __shfl_down_sync(0xffffffffu, d0_, o_);                                   \
        d1_ += __shfl_down_sync(0xffffffffu, d1_, o_);                                   \
        d2_ += __shfl_down_sync(0xffffffffu, d2_, o_);                                   \
        d3_ += __shfl_down_sync(0xffffffffu, d3_, o_);                                   \
        nv_ += __shfl_down_sync(0xffffffffu, nv_, o_);                                   \
    }                                                                                    \
    if (lane==0){                                                                        \
        float rl_ = 1.f/fmaxf(sqrtf(nv_), 1e-8f);                                        \
        float ss_ = 0.5f*((d0_*rn0##SFX*rl_+1.f)*m0##SFX + (d1_*rn1##SFX*rl_+1.f)*m1##SFX\
                        + (d2_*rn2##SFX*rl_+1.f)*m2##SFX + (d3_*rn3##SFX*rl_+1.f)*m3##SFX);\
        float lg_ = qd##SFX*(ss_ - qdm##SFX);                                            \
        out[b*S+(o)] = 1.f/(1.f+__expf(-lg_));                                           \
    }                                                                                    \
}while(0)

__global__ void __launch_bounds__(SCAN_THREADS,1) scan_kernel(
    const int* __restrict__ qseq, const int* __restrict__ haseq,
    const int* __restrict__ cseq, const int* __restrict__ itseq,
    const int* __restrict__ utseq,
    const int* __restrict__ q2c, const int* __restrict__ q2cm,
    const float* __restrict__ EC, const float* __restrict__ Wfor,
    const float* __restrict__ lat0, float* __restrict__ out)
{
    __shared__ __align__(16) float lring[4][D];   // slot t&3 = lc_t; slot 3 init = latent0
    __shared__ int sq[S], sha[S], sc[S], sit[S], sut[S];

    const int b    = blockIdx.x;
    const int tid  = threadIdx.x;
    const int lane = tid & 31;
    const bool ow  = (tid >= 128);
    const int j    = tid;               // matvec column (only valid when !ow)
    const int p    = (tid>>5) - 4;      // output warp parity (0/1)

    for (int i=tid; i<S; i+=SCAN_THREADS){
        sq[i]=qseq[b*S+i]; sha[i]=haseq[b*S+i]; sc[i]=cseq[b*S+i];
        sit[i]=itseq[b*S+i]; sut[i]=utseq[b*S+i];
    }
    if (tid < D) lring[3][tid] = lat0[b*D+tid];

    // matvec thread: full W column (128 k) packed into 64 f32x2 regs
    unsigned long long w2[64];
    float rv1=0.f, rv2=0.f, rbA=0.f, rbF=0.f;
    if (!ow){
        #pragma unroll
        for (int kk=0; kk<64; kk++){
            unsigned lo = __float_as_uint(Wfor[(2*kk  )*D + j]);
            unsigned hi = __float_as_uint(Wfor[(2*kk+1)*D + j]);
            w2[kk] = ((unsigned long long)hi << 32) | lo;
        }
        rv1=g_v1[j]; rv2=g_v2[j]; rbA=g_bA[j]; rbF=g_bF[j];
    }
    __syncthreads();   // seqs + lring[3] visible

    float cP1=0,cP2=0,cUT=0,cHA=0,cIT=0;
    if (!ow){
        int q0 = sq[0];
        cP1 = g_P1[q0*D+j]; cP2 = g_P2[q0*D+j];
        cUT = g_UT[sut[0]*D+j]; cHA = g_HA[sha[0]*D+j]; cIT = g_IT[sit[0]*D+j];
    }

    // output-warp double-buffered sets
    float EA[16], EB[16];
    float rn0A=0,rn1A=0,rn2A=0,rn3A=0,qdA=0,qdmA=0,m0A=0,m1A=0,m2A=0,m3A=0;
    float rn0B=0,rn1B=0,rn2B=0,rn3B=0,qdB=0,qdmB=0,m0B=0,m1B=0,m2B=0,m3B=0;

    for (int t=0; t<S-1; t++){
        if (!ow){
            // prefetch next step's table rows
            int q1 = sq[t+1];
            float nP1 = __ldg(&g_P1[q1*D+j]);
            float nP2 = __ldg(&g_P2[q1*D+j]);
            float nUT = __ldg(&g_UT[sut[t+1]*D+j]);
            float nHA = __ldg(&g_HA[sha[t+1]*D+j]);
            float nIT = __ldg(&g_IT[sit[t+1]*D+j]);

            const float* lprev = lring[(t+3)&3];
            float lpj = lprev[j];
            const ulonglong2* xp = (const ulonglong2*)lprev;   // broadcast LDS.128
            unsigned long long a0=0ull,a1=0ull,a2=0ull,a3=0ull;
            #pragma unroll
            for (int i=0; i<32; i+=2){
                ulonglong2 v0 = xp[i];
                ulonglong2 v1 = xp[i+1];
                ffma2(a0, v0.x, w2[2*i  ]);
                ffma2(a1, v0.y, w2[2*i+1]);
                ffma2(a2, v1.x, w2[2*i+2]);
                ffma2(a3, v1.y, w2[2*i+3]);
            }
            fadd2(a0, a1); fadd2(a2, a3); fadd2(a0, a2);
            float s = ulo(a0) + uhi(a0);

            float ctv  = (float)sc[t];
            float avec = cP1 + ctv*rv1 + cUT + cHA + rbA;
            float z    = s + cP2 + ctv*rv2 + cIT + rbF;
            float f    = 1.f/(1.f+__expf(-z));
            lring[t&3][j] = lpj*f + avec;
            cP1=nP1; cP2=nP2; cUT=nUT; cHA=nHA; cIT=nIT;

            asm volatile("bar.sync 1, 128;" ::: "memory");   // matvec-only barrier
        } else {
            if ((t&1)==0){
                // window m = t/2: load concept/scalar data for output o = t+p
                int o = t + p;
                if (o <= S-2){
                    if (((t>>1)&1)==0) OW_LOAD_SET(A, o);
                    else               OW_LOAD_SET(B, o);
                }
            } else if (t >= 3){
                // emit output o = t-3+p (slot published by the bar0 at end of step t-2)
                int o = t-3+p;
                if ((((t-3)>>1)&1)==0) OW_EMIT_SET(A, o);
                else                   OW_EMIT_SET(B, o);
            }
        }
        if (t & 1) __syncthreads();   // full barrier every 2nd step
    }
    __syncthreads();   // publish final slots (incl. step S-2 = 198)

    // epilogue: outputs 196,197 (set A, loaded t=196) and 198 (set B, loaded t=198, p=0)
    if (ow){
        { int o = 196 + p; OW_EMIT_SET(A, o); }
        if (p == 0){ OW_EMIT_SET(B, 198); }
    }
    if (tid==0) out[b*S + (S-1)] = 0.f;
}

extern "C" void kernel_launch(void* const* d_in, const int* in_sizes, int n_in,
                              void* d_out, int out_size)
{
    const int*   qseq  = (const int*)  d_in[0];
    const int*   haseq = (const int*)  d_in[1];
    const int*   cseq  = (const int*)  d_in[2];
    const int*   itseq = (const int*)  d_in[3];
    const int*   utseq = (const int*)  d_in[4];
    const int*   q2c   = (const int*)  d_in[5];
    const int*   q2cm  = (const int*)  d_in[6];
    const float* EQ    = (const float*)d_in[7];
    const float* EQd   = (const float*)d_in[8];
    const float* EC    = (const float*)d_in[9];
    const float* EIT   = (const float*)d_in[10];
    const float* EUT   = (const float*)d_in[11];
    const float* EHA   = (const float*)d_in[12];
    const float* Wfuse = (const float*)d_in[13];
    const float* bfuse = (const float*)d_in[14];
    const float* Wabs  = (const float*)d_in[15];
    const float* babs  = (const float*)d_in[16];
    const float* Wfor  = (const float*)d_in[17];
    const float* bfor  = (const float*)d_in[18];
    const float* lat0  = (const float*)d_in[19];
    float* out = (float*)d_out;

    cudaFuncSetAttribute(prepB_kernel,
                         cudaFuncAttributeMaxDynamicSharedMemorySize, SMEM_B);

    prepA_kernel<<<554, 128>>>(Wfuse, bfuse, Wabs, babs, Wfor, bfor,
                               EQd, EC, EIT, EUT, EHA);
    prepB_kernel<<<NBQ+2, 256, SMEM_B>>>(EQ, EC, q2c, q2cm, Wabs, Wfor);
    scan_kernel<<<B, SCAN_THREADS>>>(qseq, haseq, cseq, itseq, utseq,
                                     q2c, q2cm, EC, Wfor, lat0, out);
}

// round 7
// speedup vs baseline: 1.7441x; 1.0493x over previous
#include <cuda_runtime.h>
#include <math.h>

#define D   128
#define B   128
#define S   200
#define NQ  10000
#define NC  500

// ---------------- scratch tables (device globals; no allocation) ----------------
__device__ float g_M1[D*D];      // W_fuse_top @ W_absorb_top
__device__ float g_M2[D*D];      // W_fuse_top @ W_forget_bot
__device__ float g_UT[100*D];    // embed_use_time @ W_absorb_mid
__device__ float g_HA[12*D];     // embed_hint_attempt @ W_absorb_bot
__device__ float g_IT[100*D];    // embed_interval_time @ W_forget_mid
__device__ float g_s1[D];        // colsum(W_fuse_bot)
__device__ float g_v1[D];        // s1 @ W_absorb_top
__device__ float g_v2[D];        // s1 @ W_forget_bot
__device__ float g_bA[D];        // b_fuse @ W_absorb_top + b_absorb
__device__ float g_bF[D];        // b_fuse @ W_forget_bot + b_forget
__device__ float g_P1[NQ*D];     // embed_question @ M1
__device__ float g_P2[NQ*D];     // embed_question @ M2
__device__ float g_qd[NQ];       // 10*sigmoid(disc)
__device__ float g_qdm[NQ];      // sum_k qdiff_k * mask_k  (per question)
__device__ float g_rnC[NC];      // 1/max(|concept|,eps)

// packed f32x2 ops (sm_100+)
__device__ __forceinline__ void ffma2(unsigned long long &d,
                                      unsigned long long a, unsigned long long b){
    asm("fma.rn.f32x2 %0, %1, %2, %0;" : "+l"(d) : "l"(a), "l"(b));
}
__device__ __forceinline__ void fadd2(unsigned long long &d, unsigned long long a){
    asm("add.rn.f32x2 %0, %0, %1;" : "+l"(d) : "l"(a));
}
__device__ __forceinline__ float ulo(unsigned long long v){ return __uint_as_float((unsigned)v); }
__device__ __forceinline__ float uhi(unsigned long long v){ return __uint_as_float((unsigned)(v>>32)); }

// ---------------- prepA: small composite mats + tables ----------------
__global__ void __launch_bounds__(128) prepA_kernel(
    const float* __restrict__ Wfuse, const float* __restrict__ bfuse,
    const float* __restrict__ Wabs,  const float* __restrict__ babs,
    const float* __restrict__ Wfor,  const float* __restrict__ bfor,
    const float* __restrict__ EQd,   const float* __restrict__ EC,
    const float* __restrict__ EIT,   const float* __restrict__ EUT,
    const float* __restrict__ EHA)
{
    __shared__ float sh[D];
    const int tid = threadIdx.x;
    const int bid = blockIdx.x;

    if (bid < 468) {
        const float* vrow; const float* Wb; float* outp;
        if (bid < 128)      { vrow = Wfuse + bid*D;        Wb = Wabs;           outp = g_M1 + bid*D; }
        else if (bid < 256) { vrow = Wfuse + (bid-128)*D;  Wb = Wfor + 2*D*D;   outp = g_M2 + (bid-128)*D; }
        else if (bid < 356) { vrow = EUT + (bid-256)*D;    Wb = Wabs + D*D;     outp = g_UT + (bid-256)*D; }
        else if (bid < 368) { vrow = EHA + (bid-356)*D;    Wb = Wabs + 2*D*D;   outp = g_HA + (bid-356)*D; }
        else                { vrow = EIT + (bid-368)*D;    Wb = Wfor + D*D;     outp = g_IT + (bid-368)*D; }
        sh[tid] = vrow[tid];
        __syncthreads();
        float a0=0.f,a1=0.f,a2=0.f,a3=0.f,a4=0.f,a5=0.f,a6=0.f,a7=0.f;
        #pragma unroll
        for (int jj=0; jj<D; jj+=8){
            a0 += sh[jj+0]*Wb[(jj+0)*D+tid];
            a1 += sh[jj+1]*Wb[(jj+1)*D+tid];
            a2 += sh[jj+2]*Wb[(jj+2)*D+tid];
            a3 += sh[jj+3]*Wb[(jj+3)*D+tid];
            a4 += sh[jj+4]*Wb[(jj+4)*D+tid];
            a5 += sh[jj+5]*Wb[(jj+5)*D+tid];
            a6 += sh[jj+6]*Wb[(jj+6)*D+tid];
            a7 += sh[jj+7]*Wb[(jj+7)*D+tid];
        }
        outp[tid] = ((a0+a1)+(a2+a3))+((a4+a5)+(a6+a7));
    } else if (bid == 468) {
        float a0=0.f,a1=0.f,a2=0.f,a3=0.f;
        #pragma unroll
        for (int k=0;k<D;k+=4){
            a0 += Wfuse[(D+k+0)*D+tid]; a1 += Wfuse[(D+k+1)*D+tid];
            a2 += Wfuse[(D+k+2)*D+tid]; a3 += Wfuse[(D+k+3)*D+tid];
        }
        g_s1[tid]=(a0+a1)+(a2+a3);
    } else if (bid == 469) {
        sh[tid]=bfuse[tid]; __syncthreads();
        float a0=0.f,a1=0.f,a2=0.f,a3=0.f;
        #pragma unroll
        for (int k=0;k<D;k+=4){
            a0 += sh[k+0]*Wabs[(k+0)*D+tid]; a1 += sh[k+1]*Wabs[(k+1)*D+tid];
            a2 += sh[k+2]*Wabs[(k+2)*D+tid]; a3 += sh[k+3]*Wabs[(k+3)*D+tid];
        }
        g_bA[tid] = (a0+a1)+(a2+a3) + babs[tid];
    } else if (bid == 470) {
        sh[tid]=bfuse[tid]; __syncthreads();
        float a0=0.f,a1=0.f,a2=0.f,a3=0.f;
        #pragma unroll
        for (int k=0;k<D;k+=4){
            a0 += sh[k+0]*Wfor[(2*D+k+0)*D+tid]; a1 += sh[k+1]*Wfor[(2*D+k+1)*D+tid];
            a2 += sh[k+2]*Wfor[(2*D+k+2)*D+tid]; a3 += sh[k+3]*Wfor[(2*D+k+3)*D+tid];
        }
        g_bF[tid] = (a0+a1)+(a2+a3) + bfor[tid];
    } else if (bid < 475) {
        int c = (bid-471)*128 + tid;
        if (c < NC){
            float s=0.f;
            #pragma unroll
            for (int dd=0; dd<D; dd+=4){
                float4 e = *(const float4*)&EC[c*D+dd];
                s += e.x*e.x + e.y*e.y + e.z*e.z + e.w*e.w;
            }
            g_rnC[c] = 1.f/fmaxf(sqrtf(s), 1e-8f);
        }
    } else {
        int q = (bid-475)*128 + tid;
        if (q < NQ) g_qd[q] = 10.f/(1.f+__expf(-EQd[q]));
    }
}

// ---------------- prepB: P1/P2 question tables + qdm, plus v1/v2 ----------------
#define NBQ 148
#define QPB 68
#define SMEM_B ((2*D*D + 4*D) * (int)sizeof(float))

__global__ void __launch_bounds__(256) prepB_kernel(
    const float* __restrict__ EQ, const float* __restrict__ EC,
    const int* __restrict__ q2c, const int* __restrict__ q2cm,
    const float* __restrict__ Wabs, const float* __restrict__ Wfor)
{
    const int tid = threadIdx.x;
    const int bid = blockIdx.x;

    if (bid >= NBQ){                       // v1 / v2 blocks (need g_s1 from prepA)
        __shared__ float s1s[D];
        if (tid < D) s1s[tid] = g_s1[tid];
        __syncthreads();
        if (tid < D){
            const float* Wb = (bid==NBQ) ? Wabs : (Wfor + 2*D*D);
            float a0=0.f,a1=0.f,a2=0.f,a3=0.f;
            #pragma unroll
            for (int jj=0;jj<D;jj+=4){
                a0 += s1s[jj+0]*Wb[(jj+0)*D+tid]; a1 += s1s[jj+1]*Wb[(jj+1)*D+tid];
                a2 += s1s[jj+2]*Wb[(jj+2)*D+tid]; a3 += s1s[jj+3]*Wb[(jj+3)*D+tid];
            }
            float a = (a0+a1)+(a2+a3);
            if (bid==NBQ) g_v1[tid]=a; else g_v2[tid]=a;
        }
        return;
    }

    extern __shared__ float smem[];
    float* M1s = smem;            // D*D
    float* M2s = smem + D*D;      // D*D
    float* E4  = smem + 2*D*D;    // 4 questions interleaved: E4[jj*4+q]

    for (int i=tid; i<D*D; i+=256){ M1s[i]=g_M1[i]; M2s[i]=g_M2[i]; }
    __syncthreads();

    const int qbase = bid*QPB;
    for (int gg=0; gg<QPB; gg+=4){
        const int qb = qbase+gg;
        for (int i=tid; i<4*D; i+=256){
            int q = i>>7, jj = i&127;
            int qq = qb+q;
            E4[jj*4+q] = (qq<NQ) ? EQ[qq*D+jj] : 0.f;
        }
        __syncthreads();
        {
            const int halfp = tid>>7, jj = tid&127;
            const float* Ms = halfp ? M2s : M1s;
            float a0=0.f,a1=0.f,a2=0.f,a3=0.f;
            const float4* Ev = (const float4*)E4;
            #pragma unroll 8
            for (int jk=0; jk<D; jk++){
                float4 e = Ev[jk];
                float m = Ms[jk*D+jj];
                a0 += e.x*m; a1 += e.y*m; a2 += e.z*m; a3 += e.w*m;
            }
            float* P = halfp ? g_P2 : g_P1;
            if (qb+0<NQ) P[(qb+0)*D+jj]=a0;
            if (qb+1<NQ) P[(qb+1)*D+jj]=a1;
            if (qb+2<NQ) P[(qb+2)*D+jj]=a2;
            if (qb+3<NQ) P[(qb+3)*D+jj]=a3;
        }
        {   // qdm for the 4 questions, warps 0..3
            const int w = tid>>5, lane = tid&31;
            if (w<4 && (qb+w)<NQ){
                const int q = qb+w;
                int4 cid = ((const int4*)q2c)[q];
                float nrm=0.f,d0=0.f,d1=0.f,d2=0.f,d3=0.f;
                #pragma unroll
                for (int r=0;r<4;r++){
                    int jj = lane + 32*r;
                    float e = E4[jj*4+w];
                    nrm += e*e;
                    d0 += e*EC[cid.x*D+jj];
                    d1 += e*EC[cid.y*D+jj];
                    d2 += e*EC[cid.z*D+jj];
                    d3 += e*EC[cid.w*D+jj];
                }
                #pragma unroll
                for (int off=16; off; off>>=1){
                    nrm += __shfl_down_sync(0xffffffffu, nrm, off);
                    d0  += __shfl_down_sync(0xffffffffu, d0, off);
                    d1  += __shfl_down_sync(0xffffffffu, d1, off);
                    d2  += __shfl_down_sync(0xffffffffu, d2, off);
                    d3  += __shfl_down_sync(0xffffffffu, d3, off);
                }
                if (lane==0){
                    float rq = 1.f/fmaxf(sqrtf(nrm), 1e-8f);
                    int4 mm = ((const int4*)q2cm)[q];
                    float qdm =
                        0.5f*(d0*rq*g_rnC[cid.x]+1.f)*(float)mm.x +
                        0.5f*(d1*rq*g_rnC[cid.y]+1.f)*(float)mm.y +
                        0.5f*(d2*rq*g_rnC[cid.z]+1.f)*(float)mm.z +
                        0.5f*(d3*rq*g_rnC[cid.w]+1.f)*(float)mm.w;
                    g_qdm[q]=qdm;
                }
            }
        }
        __syncthreads();
    }
}

// ---------------- scan: one CTA per row; thread-local recurrence, depth-2 prefetch ----------------
#define SCAN_THREADS 192   // warps 0..3 matvec (1 column/thread), warps 4..5 output

// matvec step T consuming prefetch set (P1v..ITv) loaded at T-2; reloads the set for T+2.
// DO_BAR: emit the matvec-only barrier at the end (omit when a full __syncthreads follows).
#define MV_STEP(T, P1v,P2v,UTv,HAv,ITv, DO_BAR) do{                                      \
    float curP1_=P1v, curP2_=P2v, curUT_=UTv, curHA_=HAv, curIT_=ITv;                    \
    int tp_ = (T)+2; if (tp_ > S-1) tp_ = S-1;                                           \
    int qp_ = sq[tp_];                                                                   \
    P1v = __ldg(&g_P1[qp_*D+j]);                                                         \
    P2v = __ldg(&g_P2[qp_*D+j]);                                                         \
    UTv = __ldg(&g_UT[sut[tp_]*D+j]);                                                    \
    HAv = __ldg(&g_HA[sha[tp_]*D+j]);                                                    \
    ITv = __ldg(&g_IT[sit[tp_]*D+j]);                                                    \
    float ctv_   = (float)sc[T];                                                         \
    float basea_ = curP1_ + ctv_*rv1 + curUT_ + curHA_ + rbA;                            \
    float basez_ = curP2_ + ctv_*rv2 + curIT_ + rbF;                                     \
    const float* lprev_ = lring[((T)+3)&3];                                              \
    float lpj_ = lprev_[j];                                                              \
    const ulonglong2* xp_ = (const ulonglong2*)lprev_;                                   \
    unsigned long long a0_=0ull,a1_=0ull,a2_=0ull,a3_=0ull;                              \
    _Pragma("unroll")                                                                    \
    for (int i_=0; i_<32; i_+=2){                                                        \
        ulonglong2 v0_ = xp_[i_];                                                        \
        ulonglong2 v1_ = xp_[i_+1];                                                      \
        ffma2(a0_, v0_.x, w2[2*i_  ]);                                                   \
        ffma2(a1_, v0_.y, w2[2*i_+1]);                                                   \
        ffma2(a2_, v1_.x, w2[2*i_+2]);                                                   \
        ffma2(a3_, v1_.y, w2[2*i_+3]);                                                   \
    }                                                                                    \
    fadd2(a0_,a1_); fadd2(a2_,a3_); fadd2(a0_,a2_);                                      \
    float z_ = (ulo(a0_) + uhi(a0_)) + basez_;                                           \
    float f_ = 1.f/(1.f+__expf(-z_));                                                    \
    lring[(T)&3][j] = lpj_*f_ + basea_;                                                  \
    if (DO_BAR) asm volatile("bar.sync 1, 128;" ::: "memory");                           \
}while(0)

#define OW_LOAD_SET(SFX, o) do{                                                          \
    int q1_ = sq[(o)+1];                                                                 \
    int4 cid_ = __ldg((const int4*)q2c + q1_);                                           \
    const float* e0_ = EC + cid_.x*D + lane;                                             \
    const float* e1_ = EC + cid_.y*D + lane;                                             \
    const float* e2_ = EC + cid_.z*D + lane;                                             \
    const float* e3_ = EC + cid_.w*D + lane;                                             \
    E##SFX[0]=e0_[0];  E##SFX[1]=e0_[32];  E##SFX[2]=e0_[64];  E##SFX[3]=e0_[96];        \
    E##SFX[4]=e1_[0];  E##SFX[5]=e1_[32];  E##SFX[6]=e1_[64];  E##SFX[7]=e1_[96];        \
    E##SFX[8]=e2_[0];  E##SFX[9]=e2_[32];  E##SFX[10]=e2_[64]; E##SFX[11]=e2_[96];       \
    E##SFX[12]=e3_[0]; E##SFX[13]=e3_[32]; E##SFX[14]=e3_[64]; E##SFX[15]=e3_[96];       \
    if (lane==0){                                                                        \
        rn0##SFX=g_rnC[cid_.x]; rn1##SFX=g_rnC[cid_.y];                                  \
        rn2##SFX=g_rnC[cid_.z]; rn3##SFX=g_rnC[cid_.w];                                  \
        qd##SFX=g_qd[q1_];                                                               \
        int qt_ = sq[o]; qdm##SFX=g_qdm[qt_];                                            \
        int4 mm_ = __ldg((const int4*)q2cm + qt_);                                       \
        m0##SFX=(float)mm_.x; m1##SFX=(float)mm_.y;                                      \
        m2##SFX=(float)mm_.z; m3##SFX=(float)mm_.w;                                      \
    }                                                                                    \
}while(0)

#define OW_EMIT_SET(SFX, o) do{                                                          \
    const float* lcv_ = lring[(o)&3];                                                    \
    float x0_=lcv_[lane], x1_=lcv_[lane+32], x2_=lcv_[lane+64], x3_=lcv_[lane+96];       \
    float d0_ = x0_*E##SFX[0]  + x1_*E##SFX[1]  + x2_*E##SFX[2]  + x3_*E##SFX[3];        \
    float d1_ = x0_*E##SFX[4]  + x1_*E##SFX[5]  + x2_*E##SFX[6]  + x3_*E##SFX[7];        \
    float d2_ = x0_*E##SFX[8]  + x1_*E##SFX[9]  + x2_*E##SFX[10] + x3_*E##SFX[11];       \
    float d3_ = x0_*E##SFX[12] + x1_*E##SFX[13] + x2_*E##SFX[14] + x3_*E##SFX[15];       \
    float nv_ = x0_*x0_ + x1_*x1_ + x2_*x2_ + x3_*x3_;                                   \
    _Pragma("unroll")                                                                    \
    for (int o_=16;o_;o_>>=1){                                                           \
        d0_ += __shfl_down_sync(0xffffffffu, d0_, o_);                                   \
        d1_ += __shfl_down_sync(0xffffffffu, d1_, o_);                                   \
        d2_ += __shfl_down_sync(0xffffffffu, d2_, o_);                                   \
        d3_ += __shfl_down_sync(0xffffffffu, d3_, o_);                                   \
        nv_ += __shfl_down_sync(0xffffffffu, nv_, o_);                                   \
    }                                                                                    \
    if (lane==0){                                                                        \
        float rl_ = 1.f/fmaxf(sqrtf(nv_), 1e-8f);                                        \
        float ss_ = 0.5f*((d0_*rn0##SFX*rl_+1.f)*m0##SFX + (d1_*rn1##SFX*rl_+1.f)*m1##SFX\
                        + (d2_*rn2##SFX*rl_+1.f)*m2##SFX + (d3_*rn3##SFX*rl_+1.f)*m3##SFX);\
        float lg_ = qd##SFX*(ss_ - qdm##SFX);                                            \
        out[b*S+(o)] = 1.f/(1.f+__expf(-lg_));                                           \
    }                                                                                    \
}while(0)

// output-warp even step T: load set for output o=T+p; odd step T>=3: emit o=T-3+p
#define OW_EVEN(T) do{                                                                   \
    int o_ = (T) + p;                                                                    \
    if (o_ <= S-2){                                                                      \
        if ((((T)>>1)&1)==0) OW_LOAD_SET(A, o_);                                         \
        else                 OW_LOAD_SET(B, o_);                                         \
    }                                                                                    \
}while(0)

#define OW_ODD(T) do{                                                                    \
    if ((T) >= 3){                                                                       \
        int o_ = (T)-3+p;                                                                \
        if (((((T)-3)>>1)&1)==0) OW_EMIT_SET(A, o_);                                     \
        else                     OW_EMIT_SET(B, o_);                                     \
    }                                                                                    \
}while(0)

__global__ void __launch_bounds__(SCAN_THREADS,1) scan_kernel(
    const int* __restrict__ qseq, const int* __restrict__ haseq,
    const int* __restrict__ cseq, const int* __restrict__ itseq,
    const int* __restrict__ utseq,
    const int* __restrict__ q2c, const int* __restrict__ q2cm,
    const float* __restrict__ EC, const float* __restrict__ Wfor,
    const float* __restrict__ lat0, float* __restrict__ out)
{
    __shared__ __align__(16) float lring[4][D];   // slot t&3 = lc_t; slot 3 init = latent0
    __shared__ int sq[S], sha[S], sc[S], sit[S], sut[S];

    const int b    = blockIdx.x;
    const int tid  = threadIdx.x;
    const int lane = tid & 31;
    const bool ow  = (tid >= 128);
    const int j    = tid;               // matvec column (only valid when !ow)
    const int p    = (tid>>5) - 4;      // output warp parity (0/1)

    for (int i=tid; i<S; i+=SCAN_THREADS){
        sq[i]=qseq[b*S+i]; sha[i]=haseq[b*S+i]; sc[i]=cseq[b*S+i];
        sit[i]=itseq[b*S+i]; sut[i]=utseq[b*S+i];
    }
    if (tid < D) lring[3][tid] = lat0[b*D+tid];

    // matvec thread: full W column (128 k) packed into 64 f32x2 regs
    unsigned long long w2[64];
    float rv1=0.f, rv2=0.f, rbA=0.f, rbF=0.f;
    if (!ow){
        #pragma unroll
        for (int kk=0; kk<64; kk++){
            unsigned lo = __float_as_uint(Wfor[(2*kk  )*D + j]);
            unsigned hi = __float_as_uint(Wfor[(2*kk+1)*D + j]);
            w2[kk] = ((unsigned long long)hi << 32) | lo;
        }
        rv1=g_v1[j]; rv2=g_v2[j]; rbA=g_bA[j]; rbF=g_bF[j];
    }
    __syncthreads();   // seqs + lring[3] visible

    // depth-2 prefetch: set A = even steps, set B = odd steps
    float pA1=0,pA2=0,pA3=0,pA4=0,pA5=0;
    float pB1=0,pB2=0,pB3=0,pB4=0,pB5=0;
    if (!ow){
        int q0 = sq[0];
        pA1 = g_P1[q0*D+j]; pA2 = g_P2[q0*D+j];
        pA3 = g_UT[sut[0]*D+j]; pA4 = g_HA[sha[0]*D+j]; pA5 = g_IT[sit[0]*D+j];
        int q1 = sq[1];
        pB1 = g_P1[q1*D+j]; pB2 = g_P2[q1*D+j];
        pB3 = g_UT[sut[1]*D+j]; pB4 = g_HA[sha[1]*D+j]; pB5 = g_IT[sit[1]*D+j];
    }

    // output-warp double-buffered sets
    float EA[16], EB[16];
    float rn0A=0,rn1A=0,rn2A=0,rn3A=0,qdA=0,qdmA=0,m0A=0,m1A=0,m2A=0,m3A=0;
    float rn0B=0,rn1B=0,rn2B=0,rn3B=0,qdB=0,qdmB=0,m0B=0,m1B=0,m2B=0,m3B=0;

    // main loop unrolled x2: even step uses set A (bar1 only), odd step set B (+ full sync)
    for (int t=0; t<S-2; t+=2){
        if (!ow) MV_STEP(t,   pA1,pA2,pA3,pA4,pA5, 1);
        else     OW_EVEN(t);
        if (!ow) MV_STEP(t+1, pB1,pB2,pB3,pB4,pB5, 0);
        else     OW_ODD(t+1);
        __syncthreads();
    }
    // final even step t = S-2 = 198
    if (!ow) MV_STEP(S-2, pA1,pA2,pA3,pA4,pA5, 0);
    else     OW_EVEN(S-2);
    __syncthreads();   // publish final slots

    // epilogue: outputs 196,197 (set A, loaded t=196) and 198 (set B, loaded t=198, p=0)
    if (ow){
        { int o = 196 + p; OW_EMIT_SET(A, o); }
        if (p == 0){ OW_EMIT_SET(B, 198); }
    }
    if (tid==0) out[b*S + (S-1)] = 0.f;
}

extern "C" void kernel_launch(void* const* d_in, const int* in_sizes, int n_in,
                              void* d_out, int out_size)
{
    const int*   qseq  = (const int*)  d_in[0];
    const int*   haseq = (const int*)  d_in[1];
    const int*   cseq  = (const int*)  d_in[2];
    const int*   itseq = (const int*)  d_in[3];
    const int*   utseq = (const int*)  d_in[4];
    const int*   q2c   = (const int*)  d_in[5];
    const int*   q2cm  = (const int*)  d_in[6];
    const float* EQ    = (const float*)d_in[7];
    const float* EQd   = (const float*)d_in[8];
    const float* EC    = (const float*)d_in[9];
    const float* EIT   = (const float*)d_in[10];
    const float* EUT   = (const float*)d_in[11];
    const float* EHA   = (const float*)d_in[12];
    const float* Wfuse = (const float*)d_in[13];
    const float* bfuse = (const float*)d_in[14];
    const float* Wabs  = (const float*)d_in[15];
    const float* babs  = (const float*)d_in[16];
    const float* Wfor  = (const float*)d_in[17];
    const float* bfor  = (const float*)d_in[18];
    const float* lat0  = (const float*)d_in[19];
    float* out = (float*)d_out;

    cudaFuncSetAttribute(prepB_kernel,
                         cudaFuncAttributeMaxDynamicSharedMemorySize, SMEM_B);

    prepA_kernel<<<554, 128>>>(Wfuse, bfuse, Wabs, babs, Wfor, bfor,
                               EQd, EC, EIT, EUT, EHA);
    prepB_kernel<<<NBQ+2, 256, SMEM_B>>>(EQ, EC, q2c, q2cm, Wabs, Wfor);
    scan_kernel<<<B, SCAN_THREADS>>>(qseq, haseq, cseq, itseq, utseq,
                                     q2c, q2cm, EC, Wfor, lat0, out);
}